// round 2
// baseline (speedup 1.0000x reference)
#include <cuda_runtime.h>
#include <math_constants.h>

#define BB 8
#define TT 64
#define NP 196
#define HH 6
#define HD 64
#define CC 384
#define C3 1152
#define BT (BB*TT)          /* 512  */
#define MROWS (BT*NP)       /* 100352 */
#define QK_SCALE 0.125f

/* ---------------- scratch (static device globals; no runtime alloc) -------- */
__device__ float g_Q[(size_t)BT*HH*NP*HD];   /* [bt, h, n, d], pre-scaled */
__device__ float g_K[(size_t)BT*HH*NP*HD];
__device__ float g_V[(size_t)BT*HH*NP*HD];
__device__ float g_A[(size_t)MROWS*CC];      /* attn out, [bt, n, h*64+d] */
__device__ float g_Wp[CC*CC];                /* W_perm[o][h*64+d] = W_proj[o][d*6+h] */

/* ---------------- tiny W_proj column permute ------------------------------ */
__global__ void permute_wproj(const float* __restrict__ Wp) {
    int o = blockIdx.x;
    int c = threadIdx.x;                 /* c = h*64 + d */
    int h = c >> 6, d = c & 63;
    g_Wp[o * CC + c] = Wp[o * CC + d * HH + h];
}

/* ---------------- QKV GEMM: [100352,384] x [1152,384]^T ------------------- */
/* CTA tile 128(M) x 64(N), BK=16, 256 threads, 8x4 micro-tile.               */
/* Each 64-wide col tile maps to exactly one (q/k/v, head); epilogue scatters */
/* into g_Q/g_K/g_V with layout [bt,h,n,d], scaling Q by 1/8.                 */
__global__ __launch_bounds__(256) void qkv_gemm(const float* __restrict__ X,
                                                const float* __restrict__ W,
                                                const float* __restrict__ bias) {
    __shared__ float As[16][132];
    __shared__ float Bs[16][68];
    const int rowBase = blockIdx.x * 128;
    const int colBase = blockIdx.y * 64;
    const int tid = threadIdx.x;
    const int tx  = tid & 15;   /* N dir: 16 * 4 = 64 */
    const int ty  = tid >> 4;   /* M dir: 16 * 8 = 128 */

    float acc[8][4];
    #pragma unroll
    for (int i = 0; i < 8; i++)
        #pragma unroll
        for (int j = 0; j < 4; j++) acc[i][j] = 0.f;

    for (int k0 = 0; k0 < CC; k0 += 16) {
        #pragma unroll
        for (int it = 0; it < 2; it++) {
            int idx = tid + it * 256;          /* 512 float4 total */
            int r = idx >> 2, kq = idx & 3;
            float4 v = *(const float4*)(X + (size_t)(rowBase + r) * CC + k0 + kq * 4);
            As[kq*4+0][r] = v.x; As[kq*4+1][r] = v.y;
            As[kq*4+2][r] = v.z; As[kq*4+3][r] = v.w;
        }
        {
            int r = tid >> 2, kq = tid & 3;    /* 256 float4 total */
            float4 v = *(const float4*)(W + (size_t)(colBase + r) * CC + k0 + kq * 4);
            Bs[kq*4+0][r] = v.x; Bs[kq*4+1][r] = v.y;
            Bs[kq*4+2][r] = v.z; Bs[kq*4+3][r] = v.w;
        }
        __syncthreads();
        #pragma unroll
        for (int kk = 0; kk < 16; kk++) {
            float a[8], b[4];
            #pragma unroll
            for (int i = 0; i < 8; i++) a[i] = As[kk][ty * 8 + i];
            #pragma unroll
            for (int j = 0; j < 4; j++) b[j] = Bs[kk][tx * 4 + j];
            #pragma unroll
            for (int i = 0; i < 8; i++)
                #pragma unroll
                for (int j = 0; j < 4; j++)
                    acc[i][j] += a[i] * b[j];
        }
        __syncthreads();
    }

    const int s     = colBase / CC;             /* 0=q 1=k 2=v */
    const int rem   = colBase - s * CC;
    const int h     = rem >> 6;
    const int dBase = tx * 4;
    float* dst = (s == 0) ? g_Q : (s == 1) ? g_K : g_V;
    const float mul = (s == 0) ? QK_SCALE : 1.0f;

    float4 bv = *(const float4*)(bias + colBase + tx * 4);
    #pragma unroll
    for (int i = 0; i < 8; i++) {
        int m  = rowBase + ty * 8 + i;
        int bt = m / NP;
        int n  = m - bt * NP;
        size_t off = ((size_t)(bt * HH + h) * NP + n) * HD + dBase;
        float4 o;
        o.x = (acc[i][0] + bv.x) * mul;
        o.y = (acc[i][1] + bv.y) * mul;
        o.z = (acc[i][2] + bv.z) * mul;
        o.w = (acc[i][3] + bv.w) * mul;
        *(float4*)(dst + off) = o;
    }
}

/* ---------------- attention: one CTA per (bt,h) block --------------------- */
/* K,V (196x64 fp32 each = 100KB) resident in smem; one query row per thread */
/* with online softmax over 14-key chunks. Output written as [bt,n,h*64+d].  */
__global__ __launch_bounds__(224) void attn_kernel() {
    extern __shared__ float sm[];
    float* Ks = sm;
    float* Vs = sm + NP * HD;

    const int bx  = blockIdx.x;                /* bt*6 + h */
    const size_t base = (size_t)bx * NP * HD;
    const int tid = threadIdx.x;

    const float4* Kg = (const float4*)(g_K + base);
    const float4* Vg = (const float4*)(g_V + base);
    float4* Ks4 = (float4*)Ks;
    float4* Vs4 = (float4*)Vs;
    #pragma unroll
    for (int i = tid; i < NP * HD / 4; i += 224) {  /* 3136 = 224*14 exact */
        Ks4[i] = Kg[i];
        Vs4[i] = Vg[i];
    }
    __syncthreads();

    if (tid < NP) {
        float q[64];
        const float4* Qg = (const float4*)(g_Q + base + (size_t)tid * HD);
        #pragma unroll
        for (int i = 0; i < 16; i++) {
            float4 v = Qg[i];
            q[4*i] = v.x; q[4*i+1] = v.y; q[4*i+2] = v.z; q[4*i+3] = v.w;
        }

        float mrun = -CUDART_INF_F, l = 0.f;
        float o[64];
        #pragma unroll
        for (int d = 0; d < 64; d++) o[d] = 0.f;

        for (int c0 = 0; c0 < NP; c0 += 14) {      /* 14 chunks of 14 keys */
            float s[14];
            #pragma unroll
            for (int j = 0; j < 14; j++) {
                const float* kr = Ks + (c0 + j) * HD;
                float a = 0.f;
                #pragma unroll
                for (int d = 0; d < 64; d++) a += q[d] * kr[d];
                s[j] = a;
            }
            float cm = s[0];
            #pragma unroll
            for (int j = 1; j < 14; j++) cm = fmaxf(cm, s[j]);
            float mn = fmaxf(mrun, cm);
            float f  = __expf(mrun - mn);
            l *= f;
            #pragma unroll
            for (int d = 0; d < 64; d++) o[d] *= f;
            mrun = mn;
            #pragma unroll
            for (int j = 0; j < 14; j++) {
                float p = __expf(s[j] - mn);
                l += p;
                const float* vr = Vs + (c0 + j) * HD;
                #pragma unroll
                for (int d = 0; d < 64; d++) o[d] += p * vr[d];
            }
        }

        const float inv = 1.0f / l;
        const int bt = bx / HH, h = bx - bt * HH;
        float* dst = g_A + ((size_t)bt * NP + tid) * CC + h * HD;
        #pragma unroll
        for (int i = 0; i < 16; i++) {
            float4 v;
            v.x = o[4*i]   * inv; v.y = o[4*i+1] * inv;
            v.z = o[4*i+2] * inv; v.w = o[4*i+3] * inv;
            *(float4*)(dst + 4 * i) = v;
        }
    }
}

/* ---------------- proj GEMM: [100352,384] x W_perm^T + bias -> out -------- */
__global__ __launch_bounds__(256) void proj_gemm(const float* __restrict__ bias,
                                                 float* __restrict__ out) {
    __shared__ float As[16][132];
    __shared__ float Bs[16][68];
    const int rowBase = blockIdx.x * 128;
    const int colBase = blockIdx.y * 64;
    const int tid = threadIdx.x;
    const int tx  = tid & 15;
    const int ty  = tid >> 4;

    float acc[8][4];
    #pragma unroll
    for (int i = 0; i < 8; i++)
        #pragma unroll
        for (int j = 0; j < 4; j++) acc[i][j] = 0.f;

    for (int k0 = 0; k0 < CC; k0 += 16) {
        #pragma unroll
        for (int it = 0; it < 2; it++) {
            int idx = tid + it * 256;
            int r = idx >> 2, kq = idx & 3;
            float4 v = *(const float4*)(g_A + (size_t)(rowBase + r) * CC + k0 + kq * 4);
            As[kq*4+0][r] = v.x; As[kq*4+1][r] = v.y;
            As[kq*4+2][r] = v.z; As[kq*4+3][r] = v.w;
        }
        {
            int r = tid >> 2, kq = tid & 3;
            float4 v = *(const float4*)(g_Wp + (size_t)(colBase + r) * CC + k0 + kq * 4);
            Bs[kq*4+0][r] = v.x; Bs[kq*4+1][r] = v.y;
            Bs[kq*4+2][r] = v.z; Bs[kq*4+3][r] = v.w;
        }
        __syncthreads();
        #pragma unroll
        for (int kk = 0; kk < 16; kk++) {
            float a[8], b[4];
            #pragma unroll
            for (int i = 0; i < 8; i++) a[i] = As[kk][ty * 8 + i];
            #pragma unroll
            for (int j = 0; j < 4; j++) b[j] = Bs[kk][tx * 4 + j];
            #pragma unroll
            for (int i = 0; i < 8; i++)
                #pragma unroll
                for (int j = 0; j < 4; j++)
                    acc[i][j] += a[i] * b[j];
        }
        __syncthreads();
    }

    float4 bv = *(const float4*)(bias + colBase + tx * 4);
    #pragma unroll
    for (int i = 0; i < 8; i++) {
        int m = rowBase + ty * 8 + i;
        float4 o;
        o.x = acc[i][0] + bv.x;
        o.y = acc[i][1] + bv.y;
        o.z = acc[i][2] + bv.z;
        o.w = acc[i][3] + bv.w;
        *(float4*)(out + (size_t)m * CC + colBase + tx * 4) = o;
    }
}

/* ---------------- launch --------------------------------------------------- */
extern "C" void kernel_launch(void* const* d_in, const int* in_sizes, int n_in,
                              void* d_out, int out_size) {
    const float* x     = (const float*)d_in[0];
    const float* Wqkv  = (const float*)d_in[1];
    const float* bqkv  = (const float*)d_in[2];
    const float* Wproj = (const float*)d_in[3];
    const float* bproj = (const float*)d_in[4];
    float* out = (float*)d_out;

    const int attn_smem = 2 * NP * HD * (int)sizeof(float);   /* 100352 B */
    cudaFuncSetAttribute(attn_kernel,
                         cudaFuncAttributeMaxDynamicSharedMemorySize, attn_smem);

    permute_wproj<<<CC, CC>>>(Wproj);
    qkv_gemm<<<dim3(MROWS / 128, C3 / 64), 256>>>(x, Wqkv, bqkv);
    attn_kernel<<<BT * HH, 224, attn_smem>>>();
    proj_gemm<<<dim3(MROWS / 128, CC / 64), 256>>>(bproj, out);
}

// round 5
// speedup vs baseline: 1.5593x; 1.5593x over previous
#include <cuda_runtime.h>
#include <cuda_bf16.h>
#include <math_constants.h>
#include <cstdint>

#define BB 8
#define TT 64
#define NP 196
#define HH 6
#define HD 64
#define CC 384
#define C3 1152
#define KK 1152              /* split-K: [hi|hi|lo] x [hi|lo|hi] */
#define BT (BB*TT)           /* 512 */
#define MROWS (BT*NP)        /* 100352 */
#define QK_SCALE 0.125f

#define BK 32
#define NKT (KK/BK)          /* 36 k-tiles */
#define ROWSTRIDE 40         /* 32 bf16 + 8 pad */
#define STAGE_BYTES (128*ROWSTRIDE*2)   /* 10240 */
#define B_REGION (3*STAGE_BYTES)        /* A stages occupy [0,30720), B [30720,61440) */
#define EPS_BYTES (128*132*4)           /* 67584 epilogue staging */
#define SMEM_SZ EPS_BYTES

/* ---------------- scratch ------------------------------------------------- */
__device__ float g_Q[(size_t)BT*HH*NP*HD];            /* [bt,h,n,d] fp32, pre-scaled */
__device__ float g_K[(size_t)BT*HH*NP*HD];
__device__ float g_V[(size_t)BT*HH*NP*HD];
__device__ __nv_bfloat16 g_Xc[(size_t)MROWS*KK];      /* X split-cat  [hi|hi|lo] */
__device__ __nv_bfloat16 g_Ac[(size_t)MROWS*KK];      /* attn out split-cat */
__device__ __nv_bfloat16 g_Wqc[(size_t)C3*KK];        /* Wqkv split-cat [hi|lo|hi] */
__device__ __nv_bfloat16 g_Wpc[(size_t)CC*KK];        /* Wproj permuted split-cat */

/* ---------------- PTX helpers (sm_80-era: compile on compute_100) ---------- */
__device__ __forceinline__ uint32_t smem_u32(const void* p) {
    uint32_t a;
    asm("{ .reg .u64 t; cvta.to.shared.u64 t, %1; cvt.u32.u64 %0, t; }" : "=r"(a) : "l"(p));
    return a;
}
__device__ __forceinline__ void cpasync16(uint32_t s, const void* g) {
    asm volatile("cp.async.cg.shared.global [%0], [%1], 16;" :: "r"(s), "l"(g));
}
#define CP_COMMIT() asm volatile("cp.async.commit_group;" ::: "memory")
#define CP_WAIT1()  asm volatile("cp.async.wait_group 1;" ::: "memory")
#define CP_WAIT0()  asm volatile("cp.async.wait_group 0;" ::: "memory")

__device__ __forceinline__ void ldsm_x4(uint32_t* r, uint32_t addr) {
    asm volatile("ldmatrix.sync.aligned.m8n8.x4.shared.b16 {%0,%1,%2,%3}, [%4];"
                 : "=r"(r[0]), "=r"(r[1]), "=r"(r[2]), "=r"(r[3]) : "r"(addr));
}
__device__ __forceinline__ void ldsm_x2(uint32_t* r, uint32_t addr) {
    asm volatile("ldmatrix.sync.aligned.m8n8.x2.shared.b16 {%0,%1}, [%2];"
                 : "=r"(r[0]), "=r"(r[1]) : "r"(addr));
}
__device__ __forceinline__ void mma16816(float* c, const uint32_t* a, const uint32_t* b) {
    asm volatile("mma.sync.aligned.m16n8k16.row.col.f32.bf16.bf16.f32 "
                 "{%0,%1,%2,%3}, {%4,%5,%6,%7}, {%8,%9}, {%0,%1,%2,%3};"
                 : "+f"(c[0]), "+f"(c[1]), "+f"(c[2]), "+f"(c[3])
                 : "r"(a[0]), "r"(a[1]), "r"(a[2]), "r"(a[3]), "r"(b[0]), "r"(b[1]));
}
__device__ __forceinline__ uint32_t pk2(__nv_bfloat16 a, __nv_bfloat16 b) {
    __nv_bfloat162 t; t.x = a; t.y = b;
    return *(uint32_t*)&t;
}

/* ---------------- split conversions --------------------------------------- */
__global__ __launch_bounds__(256) void conv_A(const float* __restrict__ src) {
    int t = blockIdx.x * 256 + threadIdx.x;
    if (t >= MROWS * 96) return;
    int m = t / 96, q = t - m * 96;
    float4 v = *(const float4*)(src + (size_t)m * CC + q * 4);
    __nv_bfloat16 h0 = __float2bfloat16(v.x), h1 = __float2bfloat16(v.y);
    __nv_bfloat16 h2 = __float2bfloat16(v.z), h3 = __float2bfloat16(v.w);
    uint2 uh; uh.x = pk2(h0, h1); uh.y = pk2(h2, h3);
    uint2 ul;
    ul.x = pk2(__float2bfloat16(v.x - __bfloat162float(h0)),
               __float2bfloat16(v.y - __bfloat162float(h1)));
    ul.y = pk2(__float2bfloat16(v.z - __bfloat162float(h2)),
               __float2bfloat16(v.w - __bfloat162float(h3)));
    __nv_bfloat16* d = g_Xc + (size_t)m * KK + q * 4;
    *(uint2*)d = uh;
    *(uint2*)(d + CC) = uh;
    *(uint2*)(d + 2 * CC) = ul;
}
__global__ __launch_bounds__(256) void conv_Wq(const float* __restrict__ src) {
    int t = blockIdx.x * 256 + threadIdx.x;
    if (t >= C3 * 96) return;
    int o = t / 96, q = t - o * 96;
    float4 v = *(const float4*)(src + (size_t)o * CC + q * 4);
    __nv_bfloat16 h0 = __float2bfloat16(v.x), h1 = __float2bfloat16(v.y);
    __nv_bfloat16 h2 = __float2bfloat16(v.z), h3 = __float2bfloat16(v.w);
    uint2 uh; uh.x = pk2(h0, h1); uh.y = pk2(h2, h3);
    uint2 ul;
    ul.x = pk2(__float2bfloat16(v.x - __bfloat162float(h0)),
               __float2bfloat16(v.y - __bfloat162float(h1)));
    ul.y = pk2(__float2bfloat16(v.z - __bfloat162float(h2)),
               __float2bfloat16(v.w - __bfloat162float(h3)));
    __nv_bfloat16* d = g_Wqc + (size_t)o * KK + q * 4;
    *(uint2*)d = uh;
    *(uint2*)(d + CC) = ul;
    *(uint2*)(d + 2 * CC) = uh;
}
__global__ void conv_Wp(const float* __restrict__ src) {
    int o = blockIdx.x, c = threadIdx.x;
    int h = c >> 6, d = c & 63;
    float v = src[(size_t)o * CC + d * HH + h];
    __nv_bfloat16 hi = __float2bfloat16(v);
    __nv_bfloat16 lo = __float2bfloat16(v - __bfloat162float(hi));
    __nv_bfloat16* dst = g_Wpc + (size_t)o * KK;
    dst[c] = hi; dst[CC + c] = lo; dst[2 * CC + c] = hi;
}

/* ---------------- mma.sync GEMM mainloop: acc = A[128 rows] * B[128 cols]^T */
__device__ __forceinline__ void gemm_mainloop(const __nv_bfloat16* __restrict__ A,
                                              const __nv_bfloat16* __restrict__ Bm,
                                              int rowBase, int colBase,
                                              uint32_t sm, float acc[4][4][4]) {
    const int tid  = threadIdx.x;
    const int wid  = tid >> 5, lane = tid & 31;
    const int wr   = wid >> 2, wc = wid & 3;

    #pragma unroll
    for (int i = 0; i < 4; i++)
        #pragma unroll
        for (int j = 0; j < 4; j++)
            #pragma unroll
            for (int k = 0; k < 4; k++) acc[i][j][k] = 0.f;

    const __nv_bfloat16* Ab = A + (size_t)rowBase * KK;
    const __nv_bfloat16* Bb = Bm + (size_t)colBase * KK;
    const int r0 = tid >> 2, j0 = tid & 3;          /* prefetch coords (2 rows apart) */
    const int r1 = r0 + 64;

    /* prefetch stages 0,1 */
    #pragma unroll
    for (int s = 0; s < 2; s++) {
        int k0 = s * BK;
        uint32_t sa = sm + s * STAGE_BYTES;
        uint32_t sbuf = sm + B_REGION + s * STAGE_BYTES;
        cpasync16(sa + r0 * 80 + j0 * 16, Ab + (size_t)r0 * KK + k0 + j0 * 8);
        cpasync16(sa + r1 * 80 + j0 * 16, Ab + (size_t)r1 * KK + k0 + j0 * 8);
        cpasync16(sbuf + r0 * 80 + j0 * 16, Bb + (size_t)r0 * KK + k0 + j0 * 8);
        cpasync16(sbuf + r1 * 80 + j0 * 16, Bb + (size_t)r1 * KK + k0 + j0 * 8);
        CP_COMMIT();
    }

    /* precomputed ldmatrix intra-warp offsets (bytes) */
    const uint32_t aoff = (uint32_t)((wr * 64 + (lane & 15)) * 80 + ((lane >> 4) & 1) * 16);
    const uint32_t boff = (uint32_t)((wc * 32 + (lane & 7)) * 80 + ((lane >> 3) & 1) * 16);

    #pragma unroll 1
    for (int kt = 0; kt < NKT; kt++) {
        CP_WAIT1();
        __syncthreads();
        /* prefetch kt+2 */
        if (kt + 2 < NKT) {
            int k0 = (kt + 2) * BK;
            int st = (kt + 2) % 3;
            uint32_t sa = sm + st * STAGE_BYTES;
            uint32_t sbuf = sm + B_REGION + st * STAGE_BYTES;
            cpasync16(sa + r0 * 80 + j0 * 16, Ab + (size_t)r0 * KK + k0 + j0 * 8);
            cpasync16(sa + r1 * 80 + j0 * 16, Ab + (size_t)r1 * KK + k0 + j0 * 8);
            cpasync16(sbuf + r0 * 80 + j0 * 16, Bb + (size_t)r0 * KK + k0 + j0 * 8);
            cpasync16(sbuf + r1 * 80 + j0 * 16, Bb + (size_t)r1 * KK + k0 + j0 * 8);
        }
        CP_COMMIT();

        const int st = kt % 3;
        const uint32_t aBase = sm + st * STAGE_BYTES + aoff;
        const uint32_t bBase = sm + B_REGION + st * STAGE_BYTES + boff;
        #pragma unroll
        for (int ks = 0; ks < 2; ks++) {
            uint32_t af[4][4], bf[4][2];
            #pragma unroll
            for (int i = 0; i < 4; i++)
                ldsm_x4(af[i], aBase + (uint32_t)(i * 16 * 80 + ks * 32));
            #pragma unroll
            for (int j = 0; j < 4; j++)
                ldsm_x2(bf[j], bBase + (uint32_t)(j * 8 * 80 + ks * 32));
            #pragma unroll
            for (int i = 0; i < 4; i++)
                #pragma unroll
                for (int j = 0; j < 4; j++)
                    mma16816(acc[i][j], af[i], bf[j]);
        }
        __syncthreads();
    }
    CP_WAIT0();
    __syncthreads();
}

/* write acc -> smem eps[128][132] */
__device__ __forceinline__ void acc_to_smem(float* eps, float acc[4][4][4]) {
    const int tid = threadIdx.x, wid = tid >> 5, lane = tid & 31;
    const int wr = wid >> 2, wc = wid & 3;
    const int rl = lane >> 2, cl = 2 * (lane & 3);
    #pragma unroll
    for (int i = 0; i < 4; i++) {
        #pragma unroll
        for (int j = 0; j < 4; j++) {
            int r = wr * 64 + i * 16 + rl;
            int c = wc * 32 + j * 8 + cl;
            eps[r * 132 + c]       = acc[i][j][0];
            eps[r * 132 + c + 1]   = acc[i][j][1];
            eps[(r + 8) * 132 + c] = acc[i][j][2];
            eps[(r + 8) * 132 + c + 1] = acc[i][j][3];
        }
    }
    __syncthreads();
}

/* ---------------- QKV GEMM kernel ------------------------------------------ */
__global__ __launch_bounds__(256) void qkv_mma(const float* __restrict__ bias) {
    extern __shared__ char dynsm[];
    uint32_t sm = smem_u32(dynsm);
    const int colBase = blockIdx.x * 128;       /* x fastest: A-band L2 reuse */
    const int rowBase = blockIdx.y * 128;

    float acc[4][4][4];
    gemm_mainloop(g_Xc, g_Wqc, rowBase, colBase, sm, acc);
    float* eps = (float*)dynsm;
    acc_to_smem(eps, acc);

    const int tid = threadIdx.x, w = tid >> 5, lane = tid & 31;
    const int s  = colBase / CC;
    const int hb = (colBase - s * CC) >> 6;
    float* dst = (s == 0) ? g_Q : (s == 1) ? g_K : g_V;
    const float mul = (s == 0) ? QK_SCALE : 1.0f;
    #pragma unroll
    for (int it = 0; it < 16; it++) {
        int run = (it * 8 + w) * 2 + (lane >> 4);
        int row = run >> 1, hh = run & 1, j = lane & 15;
        int m = rowBase + row;
        int bt = m / NP, n = m - bt * NP;
        float4 v = *(float4*)(eps + row * 132 + hh * 64 + j * 4);
        float4 bv = *(const float4*)(bias + colBase + hh * 64 + j * 4);
        v.x = (v.x + bv.x) * mul; v.y = (v.y + bv.y) * mul;
        v.z = (v.z + bv.z) * mul; v.w = (v.w + bv.w) * mul;
        *(float4*)(dst + ((size_t)(bt * HH + hb + hh) * NP + n) * HD + j * 4) = v;
    }
}

/* ---------------- proj GEMM kernel ----------------------------------------- */
__global__ __launch_bounds__(256) void proj_mma(const float* __restrict__ bias,
                                                float* __restrict__ out) {
    extern __shared__ char dynsm[];
    uint32_t sm = smem_u32(dynsm);
    const int colBase = blockIdx.x * 128;
    const int rowBase = blockIdx.y * 128;

    float acc[4][4][4];
    gemm_mainloop(g_Ac, g_Wpc, rowBase, colBase, sm, acc);
    float* eps = (float*)dynsm;
    acc_to_smem(eps, acc);

    const int tid = threadIdx.x, w = tid >> 5, lane = tid & 31;
    float4 bv = *(const float4*)(bias + colBase + lane * 4);
    #pragma unroll
    for (int it = 0; it < 16; it++) {
        int row = it * 8 + w;
        int m = rowBase + row;
        float4 v = *(float4*)(eps + row * 132 + lane * 4);
        v.x += bv.x; v.y += bv.y; v.z += bv.z; v.w += bv.w;
        *(float4*)(out + (size_t)m * CC + colBase + lane * 4) = v;
    }
}

/* ---------------- attention (fp32, writes split-cat bf16) ------------------ */
__global__ __launch_bounds__(224) void attn_kernel() {
    extern __shared__ float smf[];
    float* Ks = smf;
    float* Vs = smf + NP * HD;

    const int bx = blockIdx.x;                 /* bt*6 + h */
    const size_t base = (size_t)bx * NP * HD;
    const int tid = threadIdx.x;

    const float4* Kg = (const float4*)(g_K + base);
    const float4* Vg = (const float4*)(g_V + base);
    float4* Ks4 = (float4*)Ks;
    float4* Vs4 = (float4*)Vs;
    #pragma unroll
    for (int i = tid; i < NP * HD / 4; i += 224) {
        Ks4[i] = Kg[i];
        Vs4[i] = Vg[i];
    }
    __syncthreads();

    if (tid < NP) {
        float q[64];
        const float4* Qg = (const float4*)(g_Q + base + (size_t)tid * HD);
        #pragma unroll
        for (int i = 0; i < 16; i++) {
            float4 v = Qg[i];
            q[4*i] = v.x; q[4*i+1] = v.y; q[4*i+2] = v.z; q[4*i+3] = v.w;
        }

        float mrun = -CUDART_INF_F, l = 0.f;
        float o[64];
        #pragma unroll
        for (int d = 0; d < 64; d++) o[d] = 0.f;

        for (int c0 = 0; c0 < NP; c0 += 14) {
            float s[14];
            #pragma unroll
            for (int j = 0; j < 14; j++) {
                const float* kr = Ks + (c0 + j) * HD;
                float a = 0.f;
                #pragma unroll
                for (int d = 0; d < 64; d++) a += q[d] * kr[d];
                s[j] = a;
            }
            float cm = s[0];
            #pragma unroll
            for (int j = 1; j < 14; j++) cm = fmaxf(cm, s[j]);
            float mn = fmaxf(mrun, cm);
            float f = __expf(mrun - mn);
            l *= f;
            #pragma unroll
            for (int d = 0; d < 64; d++) o[d] *= f;
            mrun = mn;
            #pragma unroll
            for (int j = 0; j < 14; j++) {
                float p = __expf(s[j] - mn);
                l += p;
                const float* vr = Vs + (c0 + j) * HD;
                #pragma unroll
                for (int d = 0; d < 64; d++) o[d] += p * vr[d];
            }
        }

        const float inv = 1.0f / l;
        const int bt = bx / HH, h = bx - bt * HH;
        __nv_bfloat16* rowp = g_Ac + (size_t)(bt * NP + tid) * KK + h * HD;
        #pragma unroll
        for (int g = 0; g < 8; g++) {
            float v0 = o[8*g+0]*inv, v1 = o[8*g+1]*inv, v2 = o[8*g+2]*inv, v3 = o[8*g+3]*inv;
            float v4 = o[8*g+4]*inv, v5 = o[8*g+5]*inv, v6 = o[8*g+6]*inv, v7 = o[8*g+7]*inv;
            __nv_bfloat16 h0=__float2bfloat16(v0), h1=__float2bfloat16(v1),
                          h2=__float2bfloat16(v2), h3=__float2bfloat16(v3),
                          h4=__float2bfloat16(v4), h5=__float2bfloat16(v5),
                          h6=__float2bfloat16(v6), h7=__float2bfloat16(v7);
            uint4 uh;
            uh.x = pk2(h0,h1); uh.y = pk2(h2,h3); uh.z = pk2(h4,h5); uh.w = pk2(h6,h7);
            uint4 ul;
            ul.x = pk2(__float2bfloat16(v0-__bfloat162float(h0)), __float2bfloat16(v1-__bfloat162float(h1)));
            ul.y = pk2(__float2bfloat16(v2-__bfloat162float(h2)), __float2bfloat16(v3-__bfloat162float(h3)));
            ul.z = pk2(__float2bfloat16(v4-__bfloat162float(h4)), __float2bfloat16(v5-__bfloat162float(h5)));
            ul.w = pk2(__float2bfloat16(v6-__bfloat162float(h6)), __float2bfloat16(v7-__bfloat162float(h7)));
            *(uint4*)(rowp + 8*g) = uh;
            *(uint4*)(rowp + CC + 8*g) = uh;
            *(uint4*)(rowp + 2*CC + 8*g) = ul;
        }
    }
}

/* ---------------- launch --------------------------------------------------- */
extern "C" void kernel_launch(void* const* d_in, const int* in_sizes, int n_in,
                              void* d_out, int out_size) {
    const float* x     = (const float*)d_in[0];
    const float* Wqkv  = (const float*)d_in[1];
    const float* bqkv  = (const float*)d_in[2];
    const float* Wproj = (const float*)d_in[3];
    const float* bproj = (const float*)d_in[4];
    float* out = (float*)d_out;

    const int attn_smem = 2 * NP * HD * (int)sizeof(float);
    cudaFuncSetAttribute(attn_kernel, cudaFuncAttributeMaxDynamicSharedMemorySize, attn_smem);
    cudaFuncSetAttribute(qkv_mma,  cudaFuncAttributeMaxDynamicSharedMemorySize, SMEM_SZ);
    cudaFuncSetAttribute(proj_mma, cudaFuncAttributeMaxDynamicSharedMemorySize, SMEM_SZ);

    conv_A <<<(MROWS * 96 + 255) / 256, 256>>>(x);
    conv_Wq<<<(C3 * 96 + 255) / 256, 256>>>(Wqkv);
    conv_Wp<<<CC, CC>>>(Wproj);
    qkv_mma<<<dim3(C3 / 128, MROWS / 128), 256, SMEM_SZ>>>(bqkv);
    attn_kernel<<<BT * HH, 224, attn_smem>>>();
    proj_mma<<<dim3(CC / 128, MROWS / 128), 256, SMEM_SZ>>>(bproj, out);
}

// round 6
// speedup vs baseline: 1.6391x; 1.0512x over previous
#include <cuda_runtime.h>
#include <cuda_bf16.h>
#include <math_constants.h>
#include <cstdint>

#define BB 8
#define TT 64
#define NP 196
#define HH 6
#define HD 64
#define CC 384
#define C3 1152
#define KK 1152              /* split-K: [hi|hi|lo] x [hi|lo|hi] */
#define BT (BB*TT)           /* 512 */
#define MROWS (BT*NP)        /* 100352 */
#define NBH (BT*HH)          /* 3072 */
#define QK_SCALE 0.125f

#define BK 32
#define NKT (KK/BK)          /* 36 k-tiles */
#define STAGE_BYTES (128*40*2)          /* 10240 */
#define B_REGION (3*STAGE_BYTES)
#define EPS_BYTES (128*132*4)           /* 67584 epilogue staging */
#define SMEM_SZ EPS_BYTES

/* attention smem layout (bytes) */
#define KSTRB 144            /* K/Q smem row stride: 72 bf16 */
#define VSTRB 432            /* Vt smem row stride: 216 bf16 */
#define SM_QH 0
#define SM_QL 29952          /* 208*144 */
#define SM_KH 59904
#define SM_KL 89856
#define SM_VH 119808
#define SM_VL 147456         /* +64*432 */
#define ATT_SMEM 175104

/* ---------------- scratch ------------------------------------------------- */
__device__ __nv_bfloat16 g_Qh[(size_t)NBH*NP*HD];     /* [bh][n][d] hi */
__device__ __nv_bfloat16 g_Ql[(size_t)NBH*NP*HD];
__device__ __nv_bfloat16 g_Kh[(size_t)NBH*NP*HD];
__device__ __nv_bfloat16 g_Kl[(size_t)NBH*NP*HD];
__device__ __nv_bfloat16 g_Vth[(size_t)NBH*HD*NP];    /* [bh][d][n] hi (transposed) */
__device__ __nv_bfloat16 g_Vtl[(size_t)NBH*HD*NP];
__device__ __nv_bfloat16 g_Xc[(size_t)MROWS*KK];      /* X split-cat  [hi|hi|lo] */
__device__ __nv_bfloat16 g_Ac[(size_t)MROWS*KK];      /* attn out split-cat */
__device__ __nv_bfloat16 g_Wqc[(size_t)C3*KK];        /* Wqkv split-cat [hi|lo|hi] */
__device__ __nv_bfloat16 g_Wpc[(size_t)CC*KK];        /* Wproj permuted split-cat */

/* ---------------- PTX helpers --------------------------------------------- */
__device__ __forceinline__ uint32_t smem_u32(const void* p) {
    uint32_t a;
    asm("{ .reg .u64 t; cvta.to.shared.u64 t, %1; cvt.u32.u64 %0, t; }" : "=r"(a) : "l"(p));
    return a;
}
__device__ __forceinline__ void cpasync16(uint32_t s, const void* g) {
    asm volatile("cp.async.cg.shared.global [%0], [%1], 16;" :: "r"(s), "l"(g));
}
#define CP_COMMIT() asm volatile("cp.async.commit_group;" ::: "memory")
#define CP_WAIT1()  asm volatile("cp.async.wait_group 1;" ::: "memory")
#define CP_WAIT0()  asm volatile("cp.async.wait_group 0;" ::: "memory")

__device__ __forceinline__ void ldsm_x4(uint32_t* r, uint32_t addr) {
    asm volatile("ldmatrix.sync.aligned.m8n8.x4.shared.b16 {%0,%1,%2,%3}, [%4];"
                 : "=r"(r[0]), "=r"(r[1]), "=r"(r[2]), "=r"(r[3]) : "r"(addr));
}
__device__ __forceinline__ void ldsm_x2(uint32_t* r, uint32_t addr) {
    asm volatile("ldmatrix.sync.aligned.m8n8.x2.shared.b16 {%0,%1}, [%2];"
                 : "=r"(r[0]), "=r"(r[1]) : "r"(addr));
}
__device__ __forceinline__ void mma16816(float* c, const uint32_t* a, const uint32_t* b) {
    asm volatile("mma.sync.aligned.m16n8k16.row.col.f32.bf16.bf16.f32 "
                 "{%0,%1,%2,%3}, {%4,%5,%6,%7}, {%8,%9}, {%0,%1,%2,%3};"
                 : "+f"(c[0]), "+f"(c[1]), "+f"(c[2]), "+f"(c[3])
                 : "r"(a[0]), "r"(a[1]), "r"(a[2]), "r"(a[3]), "r"(b[0]), "r"(b[1]));
}
__device__ __forceinline__ uint32_t pk2(__nv_bfloat16 a, __nv_bfloat16 b) {
    __nv_bfloat162 t; t.x = a; t.y = b;
    return *(uint32_t*)&t;
}

/* ---------------- split conversions --------------------------------------- */
__global__ __launch_bounds__(256) void conv_A(const float* __restrict__ src) {
    int t = blockIdx.x * 256 + threadIdx.x;
    if (t >= MROWS * 96) return;
    int m = t / 96, q = t - m * 96;
    float4 v = *(const float4*)(src + (size_t)m * CC + q * 4);
    __nv_bfloat16 h0 = __float2bfloat16(v.x), h1 = __float2bfloat16(v.y);
    __nv_bfloat16 h2 = __float2bfloat16(v.z), h3 = __float2bfloat16(v.w);
    uint2 uh; uh.x = pk2(h0, h1); uh.y = pk2(h2, h3);
    uint2 ul;
    ul.x = pk2(__float2bfloat16(v.x - __bfloat162float(h0)),
               __float2bfloat16(v.y - __bfloat162float(h1)));
    ul.y = pk2(__float2bfloat16(v.z - __bfloat162float(h2)),
               __float2bfloat16(v.w - __bfloat162float(h3)));
    __nv_bfloat16* d = g_Xc + (size_t)m * KK + q * 4;
    *(uint2*)d = uh;
    *(uint2*)(d + CC) = uh;
    *(uint2*)(d + 2 * CC) = ul;
}
__global__ __launch_bounds__(256) void conv_Wq(const float* __restrict__ src) {
    int t = blockIdx.x * 256 + threadIdx.x;
    if (t >= C3 * 96) return;
    int o = t / 96, q = t - o * 96;
    float4 v = *(const float4*)(src + (size_t)o * CC + q * 4);
    __nv_bfloat16 h0 = __float2bfloat16(v.x), h1 = __float2bfloat16(v.y);
    __nv_bfloat16 h2 = __float2bfloat16(v.z), h3 = __float2bfloat16(v.w);
    uint2 uh; uh.x = pk2(h0, h1); uh.y = pk2(h2, h3);
    uint2 ul;
    ul.x = pk2(__float2bfloat16(v.x - __bfloat162float(h0)),
               __float2bfloat16(v.y - __bfloat162float(h1)));
    ul.y = pk2(__float2bfloat16(v.z - __bfloat162float(h2)),
               __float2bfloat16(v.w - __bfloat162float(h3)));
    __nv_bfloat16* d = g_Wqc + (size_t)o * KK + q * 4;
    *(uint2*)d = uh;
    *(uint2*)(d + CC) = ul;
    *(uint2*)(d + 2 * CC) = uh;
}
__global__ void conv_Wp(const float* __restrict__ src) {
    int o = blockIdx.x, c = threadIdx.x;
    int h = c >> 6, d = c & 63;
    float v = src[(size_t)o * CC + d * HH + h];
    __nv_bfloat16 hi = __float2bfloat16(v);
    __nv_bfloat16 lo = __float2bfloat16(v - __bfloat162float(hi));
    __nv_bfloat16* dst = g_Wpc + (size_t)o * KK;
    dst[c] = hi; dst[CC + c] = lo; dst[2 * CC + c] = hi;
}

/* ---------------- mma.sync GEMM mainloop ---------------------------------- */
__device__ __forceinline__ void gemm_mainloop(const __nv_bfloat16* __restrict__ A,
                                              const __nv_bfloat16* __restrict__ Bm,
                                              int rowBase, int colBase,
                                              uint32_t sm, float acc[4][4][4]) {
    const int tid  = threadIdx.x;
    const int wid  = tid >> 5, lane = tid & 31;
    const int wr   = wid >> 2, wc = wid & 3;

    #pragma unroll
    for (int i = 0; i < 4; i++)
        #pragma unroll
        for (int j = 0; j < 4; j++)
            #pragma unroll
            for (int k = 0; k < 4; k++) acc[i][j][k] = 0.f;

    const __nv_bfloat16* Ab = A + (size_t)rowBase * KK;
    const __nv_bfloat16* Bb = Bm + (size_t)colBase * KK;
    const int r0 = tid >> 2, j0 = tid & 3;
    const int r1 = r0 + 64;

    #pragma unroll
    for (int s = 0; s < 2; s++) {
        int k0 = s * BK;
        uint32_t sa = sm + s * STAGE_BYTES;
        uint32_t sbuf = sm + B_REGION + s * STAGE_BYTES;
        cpasync16(sa + r0 * 80 + j0 * 16, Ab + (size_t)r0 * KK + k0 + j0 * 8);
        cpasync16(sa + r1 * 80 + j0 * 16, Ab + (size_t)r1 * KK + k0 + j0 * 8);
        cpasync16(sbuf + r0 * 80 + j0 * 16, Bb + (size_t)r0 * KK + k0 + j0 * 8);
        cpasync16(sbuf + r1 * 80 + j0 * 16, Bb + (size_t)r1 * KK + k0 + j0 * 8);
        CP_COMMIT();
    }

    const uint32_t aoff = (uint32_t)((wr * 64 + (lane & 15)) * 80 + ((lane >> 4) & 1) * 16);
    const uint32_t boff = (uint32_t)((wc * 32 + (lane & 7)) * 80 + ((lane >> 3) & 1) * 16);

    #pragma unroll 1
    for (int kt = 0; kt < NKT; kt++) {
        CP_WAIT1();
        __syncthreads();
        if (kt + 2 < NKT) {
            int k0 = (kt + 2) * BK;
            int st = (kt + 2) % 3;
            uint32_t sa = sm + st * STAGE_BYTES;
            uint32_t sbuf = sm + B_REGION + st * STAGE_BYTES;
            cpasync16(sa + r0 * 80 + j0 * 16, Ab + (size_t)r0 * KK + k0 + j0 * 8);
            cpasync16(sa + r1 * 80 + j0 * 16, Ab + (size_t)r1 * KK + k0 + j0 * 8);
            cpasync16(sbuf + r0 * 80 + j0 * 16, Bb + (size_t)r0 * KK + k0 + j0 * 8);
            cpasync16(sbuf + r1 * 80 + j0 * 16, Bb + (size_t)r1 * KK + k0 + j0 * 8);
        }
        CP_COMMIT();

        const int st = kt % 3;
        const uint32_t aBase = sm + st * STAGE_BYTES + aoff;
        const uint32_t bBase = sm + B_REGION + st * STAGE_BYTES + boff;
        #pragma unroll
        for (int ks = 0; ks < 2; ks++) {
            uint32_t af[4][4], bf[4][2];
            #pragma unroll
            for (int i = 0; i < 4; i++)
                ldsm_x4(af[i], aBase + (uint32_t)(i * 16 * 80 + ks * 32));
            #pragma unroll
            for (int j = 0; j < 4; j++)
                ldsm_x2(bf[j], bBase + (uint32_t)(j * 8 * 80 + ks * 32));
            #pragma unroll
            for (int i = 0; i < 4; i++)
                #pragma unroll
                for (int j = 0; j < 4; j++)
                    mma16816(acc[i][j], af[i], bf[j]);
        }
        __syncthreads();
    }
    CP_WAIT0();
    __syncthreads();
}

__device__ __forceinline__ void acc_to_smem(float* eps, float acc[4][4][4]) {
    const int tid = threadIdx.x, wid = tid >> 5, lane = tid & 31;
    const int wr = wid >> 2, wc = wid & 3;
    const int rl = lane >> 2, cl = 2 * (lane & 3);
    #pragma unroll
    for (int i = 0; i < 4; i++) {
        #pragma unroll
        for (int j = 0; j < 4; j++) {
            int r = wr * 64 + i * 16 + rl;
            int c = wc * 32 + j * 8 + cl;
            eps[r * 132 + c]       = acc[i][j][0];
            eps[r * 132 + c + 1]   = acc[i][j][1];
            eps[(r + 8) * 132 + c] = acc[i][j][2];
            eps[(r + 8) * 132 + c + 1] = acc[i][j][3];
        }
    }
    __syncthreads();
}

/* ---------------- QKV GEMM kernel: epilogue emits split bf16 --------------- */
__global__ __launch_bounds__(256) void qkv_mma(const float* __restrict__ bias) {
    extern __shared__ char dynsm[];
    uint32_t sm = smem_u32(dynsm);
    const int colBase = blockIdx.x * 128;
    const int rowBase = blockIdx.y * 128;

    float acc[4][4][4];
    gemm_mainloop(g_Xc, g_Wqc, rowBase, colBase, sm, acc);
    float* eps = (float*)dynsm;
    acc_to_smem(eps, acc);

    const int tid = threadIdx.x, w = tid >> 5, lane = tid & 31;
    const int s  = colBase / CC;
    const int hb = (colBase - s * CC) >> 6;
    const float mul = (s == 0) ? QK_SCALE : 1.0f;
    #pragma unroll
    for (int it = 0; it < 16; it++) {
        int run = (it * 8 + w) * 2 + (lane >> 4);
        int row = run >> 1, hh = run & 1, j = lane & 15;
        int m = rowBase + row;
        int bt = m / NP, n = m - bt * NP;
        float4 v = *(float4*)(eps + row * 132 + hh * 64 + j * 4);
        float4 bv = *(const float4*)(bias + colBase + hh * 64 + j * 4);
        v.x = (v.x + bv.x) * mul; v.y = (v.y + bv.y) * mul;
        v.z = (v.z + bv.z) * mul; v.w = (v.w + bv.w) * mul;
        __nv_bfloat16 h0 = __float2bfloat16(v.x), h1 = __float2bfloat16(v.y);
        __nv_bfloat16 h2 = __float2bfloat16(v.z), h3 = __float2bfloat16(v.w);
        __nv_bfloat16 l0 = __float2bfloat16(v.x - __bfloat162float(h0));
        __nv_bfloat16 l1 = __float2bfloat16(v.y - __bfloat162float(h1));
        __nv_bfloat16 l2 = __float2bfloat16(v.z - __bfloat162float(h2));
        __nv_bfloat16 l3 = __float2bfloat16(v.w - __bfloat162float(h3));
        int bh = bt * HH + hb + hh;
        if (s < 2) {
            uint2 uh; uh.x = pk2(h0, h1); uh.y = pk2(h2, h3);
            uint2 ul; ul.x = pk2(l0, l1); ul.y = pk2(l2, l3);
            size_t off = ((size_t)bh * NP + n) * HD + j * 4;
            if (s == 0) { *(uint2*)(g_Qh + off) = uh; *(uint2*)(g_Ql + off) = ul; }
            else        { *(uint2*)(g_Kh + off) = uh; *(uint2*)(g_Kl + off) = ul; }
        } else {
            size_t tb = ((size_t)bh * HD + j * 4) * NP + n;
            g_Vth[tb]          = h0; g_Vtl[tb]          = l0;
            g_Vth[tb + NP]     = h1; g_Vtl[tb + NP]     = l1;
            g_Vth[tb + 2*NP]   = h2; g_Vtl[tb + 2*NP]   = l2;
            g_Vth[tb + 3*NP]   = h3; g_Vtl[tb + 3*NP]   = l3;
        }
    }
}

/* ---------------- proj GEMM kernel ----------------------------------------- */
__global__ __launch_bounds__(256) void proj_mma(const float* __restrict__ bias,
                                                float* __restrict__ out) {
    extern __shared__ char dynsm[];
    uint32_t sm = smem_u32(dynsm);
    const int colBase = blockIdx.x * 128;
    const int rowBase = blockIdx.y * 128;

    float acc[4][4][4];
    gemm_mainloop(g_Ac, g_Wpc, rowBase, colBase, sm, acc);
    float* eps = (float*)dynsm;
    acc_to_smem(eps, acc);

    const int tid = threadIdx.x, w = tid >> 5, lane = tid & 31;
    float4 bv = *(const float4*)(bias + colBase + lane * 4);
    #pragma unroll
    for (int it = 0; it < 16; it++) {
        int row = it * 8 + w;
        int m = rowBase + row;
        float4 v = *(float4*)(eps + row * 132 + lane * 4);
        v.x += bv.x; v.y += bv.y; v.z += bv.z; v.w += bv.w;
        *(float4*)(out + (size_t)m * CC + colBase + lane * 4) = v;
    }
}

/* ---------------- attention via mma.sync ----------------------------------- */
/* One CTA per (bt,h). 13 warps x 16 query rows (pad 196->208).               */
/* S = Qhi*Khi + Qhi*Klo + Qlo*Khi ; softmax without max-sub (|s| small);     */
/* O = Phi*Vhi + Phi*Vlo + Plo*Vhi. Keys in 2 chunks: 112 (14 nt) + 96 (12).  */
template<int NT>
__device__ __forceinline__ void attn_chunk(uint32_t sb, int lane, int cbase,
                                           const uint32_t qh[4][4], const uint32_t ql[4][4],
                                           float o[8][4], float& lp0, float& lp1) {
    float s[NT][4];
    #pragma unroll
    for (int t = 0; t < NT; t++)
        #pragma unroll
        for (int e = 0; e < 4; e++) s[t][e] = 0.f;

    /* --- QK --- */
    #pragma unroll
    for (int t = 0; t < NT; t++) {
        #pragma unroll
        for (int ks = 0; ks < 4; ks++) {
            uint32_t bh[2], bl[2];
            uint32_t off = (uint32_t)((cbase + t * 8 + (lane & 7)) * KSTRB
                                      + ks * 32 + ((lane >> 3) & 1) * 16);
            ldsm_x2(bh, sb + SM_KH + off);
            ldsm_x2(bl, sb + SM_KL + off);
            mma16816(s[t], qh[ks], bh);
            mma16816(s[t], qh[ks], bl);
            mma16816(s[t], ql[ks], bh);
        }
    }

    /* --- exp + mask + pack P (C-frag -> A-frag identity) --- */
    uint32_t phi[NT/2][4], plo[NT/2][4];
    #pragma unroll
    for (int t = 0; t < NT; t++) {
        int c0 = cbase + t * 8 + 2 * (lane & 3);
        float p0 = (c0     < NP) ? __expf(s[t][0]) : 0.f;
        float p1 = (c0 + 1 < NP) ? __expf(s[t][1]) : 0.f;
        float p2 = (c0     < NP) ? __expf(s[t][2]) : 0.f;
        float p3 = (c0 + 1 < NP) ? __expf(s[t][3]) : 0.f;
        lp0 += p0 + p1;
        lp1 += p2 + p3;
        __nv_bfloat16 h0 = __float2bfloat16(p0), h1 = __float2bfloat16(p1);
        __nv_bfloat16 h2 = __float2bfloat16(p2), h3 = __float2bfloat16(p3);
        int j = t >> 1, oreg = (t & 1) * 2;
        phi[j][oreg]     = pk2(h0, h1);
        phi[j][oreg + 1] = pk2(h2, h3);
        plo[j][oreg]     = pk2(__float2bfloat16(p0 - __bfloat162float(h0)),
                               __float2bfloat16(p1 - __bfloat162float(h1)));
        plo[j][oreg + 1] = pk2(__float2bfloat16(p2 - __bfloat162float(h2)),
                               __float2bfloat16(p3 - __bfloat162float(h3)));
    }

    /* --- PV --- */
    #pragma unroll
    for (int j = 0; j < NT / 2; j++) {
        #pragma unroll
        for (int nd = 0; nd < 8; nd++) {
            uint32_t bh[2], bl[2];
            uint32_t off = (uint32_t)((nd * 8 + (lane & 7)) * VSTRB
                                      + (cbase + j * 16) * 2 + ((lane >> 3) & 1) * 16);
            ldsm_x2(bh, sb + SM_VH + off);
            ldsm_x2(bl, sb + SM_VL + off);
            mma16816(o[nd], phi[j], bh);
            mma16816(o[nd], phi[j], bl);
            mma16816(o[nd], plo[j], bh);
        }
    }
}

__global__ __launch_bounds__(416, 1) void attn_mma() {
    extern __shared__ char smc[];
    uint32_t sb = smem_u32(smc);
    const int bx = blockIdx.x;                 /* bt*6 + h */
    const int tid = threadIdx.x, wid = tid >> 5, lane = tid & 31;

    /* zero-fill (covers pad rows/cols) */
    for (int i = tid; i < ATT_SMEM / 16; i += 416)
        ((uint4*)smc)[i] = make_uint4(0, 0, 0, 0);
    __syncthreads();

    const size_t base = (size_t)bx * NP * HD;
    /* dense Q/K copy: 196 rows x 8 uint4 each */
    for (int i = tid; i < NP * 8; i += 416) {
        int r = i >> 3, j = i & 7;
        uint32_t doff = (uint32_t)(r * KSTRB + j * 16);
        *(uint4*)(smc + SM_QH + doff) = ((const uint4*)(g_Qh + base))[i];
        *(uint4*)(smc + SM_QL + doff) = ((const uint4*)(g_Ql + base))[i];
        *(uint4*)(smc + SM_KH + doff) = ((const uint4*)(g_Kh + base))[i];
        *(uint4*)(smc + SM_KL + doff) = ((const uint4*)(g_Kl + base))[i];
    }
    /* Vt copy: 64 rows x 49 uint2 each (392B rows) */
    for (int i = tid; i < HD * 49; i += 416) {
        int r = i / 49, j = i - r * 49;
        uint32_t doff = (uint32_t)(r * VSTRB + j * 8);
        *(uint2*)(smc + SM_VH + doff) = ((const uint2*)(g_Vth + base))[i];
        *(uint2*)(smc + SM_VL + doff) = ((const uint2*)(g_Vtl + base))[i];
    }
    __syncthreads();

    /* Q fragments for this warp's 16 rows */
    uint32_t qh[4][4], ql[4][4];
    {
        uint32_t qoff = (uint32_t)((wid * 16 + (lane & 15)) * KSTRB + ((lane >> 4) & 1) * 16);
        #pragma unroll
        for (int ks = 0; ks < 4; ks++) {
            ldsm_x4(qh[ks], sb + SM_QH + qoff + ks * 32);
            ldsm_x4(ql[ks], sb + SM_QL + qoff + ks * 32);
        }
    }

    float o[8][4];
    #pragma unroll
    for (int nd = 0; nd < 8; nd++)
        #pragma unroll
        for (int e = 0; e < 4; e++) o[nd][e] = 0.f;
    float lp0 = 0.f, lp1 = 0.f;

    attn_chunk<14>(sb, lane, 0,   qh, ql, o, lp0, lp1);
    attn_chunk<12>(sb, lane, 112, qh, ql, o, lp0, lp1);

    /* row-sum reduce across the quad holding the same rows */
    lp0 += __shfl_xor_sync(0xFFFFFFFFu, lp0, 1);
    lp0 += __shfl_xor_sync(0xFFFFFFFFu, lp0, 2);
    lp1 += __shfl_xor_sync(0xFFFFFFFFu, lp1, 1);
    lp1 += __shfl_xor_sync(0xFFFFFFFFu, lp1, 2);
    const float inv0 = 1.0f / lp0, inv1 = 1.0f / lp1;

    /* store split-cat rows of g_Ac */
    const int bt = bx / HH, h = bx - bt * HH;
    const int r0 = wid * 16 + (lane >> 2);
    const int cl = 2 * (lane & 3);
    #pragma unroll
    for (int nd = 0; nd < 8; nd++) {
        int col = h * HD + nd * 8 + cl;
        if (r0 < NP) {
            float v0 = o[nd][0] * inv0, v1 = o[nd][1] * inv0;
            __nv_bfloat16 a0 = __float2bfloat16(v0), a1 = __float2bfloat16(v1);
            uint32_t uh = pk2(a0, a1);
            uint32_t ul = pk2(__float2bfloat16(v0 - __bfloat162float(a0)),
                              __float2bfloat16(v1 - __bfloat162float(a1)));
            size_t ro = ((size_t)bt * NP + r0) * KK + col;
            *(uint32_t*)(g_Ac + ro)          = uh;
            *(uint32_t*)(g_Ac + ro + CC)     = uh;
            *(uint32_t*)(g_Ac + ro + 2 * CC) = ul;
        }
        if (r0 + 8 < NP) {
            float v2 = o[nd][2] * inv1, v3 = o[nd][3] * inv1;
            __nv_bfloat16 a2 = __float2bfloat16(v2), a3 = __float2bfloat16(v3);
            uint32_t uh = pk2(a2, a3);
            uint32_t ul = pk2(__float2bfloat16(v2 - __bfloat162float(a2)),
                              __float2bfloat16(v3 - __bfloat162float(a3)));
            size_t ro = ((size_t)bt * NP + r0 + 8) * KK + col;
            *(uint32_t*)(g_Ac + ro)          = uh;
            *(uint32_t*)(g_Ac + ro + CC)     = uh;
            *(uint32_t*)(g_Ac + ro + 2 * CC) = ul;
        }
    }
}

/* ---------------- launch --------------------------------------------------- */
extern "C" void kernel_launch(void* const* d_in, const int* in_sizes, int n_in,
                              void* d_out, int out_size) {
    const float* x     = (const float*)d_in[0];
    const float* Wqkv  = (const float*)d_in[1];
    const float* bqkv  = (const float*)d_in[2];
    const float* Wproj = (const float*)d_in[3];
    const float* bproj = (const float*)d_in[4];
    float* out = (float*)d_out;

    cudaFuncSetAttribute(attn_mma, cudaFuncAttributeMaxDynamicSharedMemorySize, ATT_SMEM);
    cudaFuncSetAttribute(qkv_mma,  cudaFuncAttributeMaxDynamicSharedMemorySize, SMEM_SZ);
    cudaFuncSetAttribute(proj_mma, cudaFuncAttributeMaxDynamicSharedMemorySize, SMEM_SZ);

    conv_A <<<(MROWS * 96 + 255) / 256, 256>>>(x);
    conv_Wq<<<(C3 * 96 + 255) / 256, 256>>>(Wqkv);
    conv_Wp<<<CC, CC>>>(Wproj);
    qkv_mma<<<dim3(C3 / 128, MROWS / 128), 256, SMEM_SZ>>>(bqkv);
    attn_mma<<<NBH, 416, ATT_SMEM>>>();
    proj_mma<<<dim3(CC / 128, MROWS / 128), 256, SMEM_SZ>>>(bproj, out);
}

// round 7
// speedup vs baseline: 2.2391x; 1.3661x over previous
#include <cuda_runtime.h>
#include <cuda_bf16.h>
#include <math_constants.h>
#include <cstdint>

#define BB 8
#define TT 64
#define NP 196
#define HH 6
#define HD 64
#define CC 384
#define C3 1152
#define KK 1152              /* logical split-K: [hi|hi|lo] x [hi|lo|hi] */
#define AKW 768              /* stored A width: [hi|lo], hi reused for k<768 */
#define BT (BB*TT)           /* 512 */
#define MROWS (BT*NP)        /* 100352 */
#define NBH (BT*HH)          /* 3072 */
#define QK_SCALE 0.125f

#define BK 32
#define NKT (KK/BK)          /* 36 k-tiles */
#define STAGE_BYTES (128*40*2)          /* 10240 */
#define B_REGION (4*STAGE_BYTES)        /* A: 4 stages, then B: 4 stages */
#define EPS_BYTES (128*132*4)           /* 67584 epilogue staging */
#define SMEM_SZ (8*STAGE_BYTES)         /* 81920 */

/* attention smem: Q,K,V hi/lo, each 208 rows x 144B */
#define KSTRB 144
#define REG_SZ (208*KSTRB)   /* 29952 */
#define SM_QH 0
#define SM_QL (1*REG_SZ)
#define SM_KH (2*REG_SZ)
#define SM_KL (3*REG_SZ)
#define SM_VH (4*REG_SZ)
#define SM_VL (5*REG_SZ)
#define ATT_SMEM (6*REG_SZ)  /* 179712 */

/* ---------------- scratch ------------------------------------------------- */
__device__ __nv_bfloat16 g_Qh[(size_t)NBH*NP*HD];     /* [bh][n][d] hi */
__device__ __nv_bfloat16 g_Ql[(size_t)NBH*NP*HD];
__device__ __nv_bfloat16 g_Kh[(size_t)NBH*NP*HD];
__device__ __nv_bfloat16 g_Kl[(size_t)NBH*NP*HD];
__device__ __nv_bfloat16 g_Vh[(size_t)NBH*NP*HD];     /* [bh][n][d] hi (row layout) */
__device__ __nv_bfloat16 g_Vl[(size_t)NBH*NP*HD];
__device__ __nv_bfloat16 g_Xc[(size_t)MROWS*AKW];     /* X [hi|lo], 768 wide */
__device__ __nv_bfloat16 g_Ac[(size_t)MROWS*AKW];     /* attn out [hi|lo] */
__device__ __nv_bfloat16 g_Wqc[(size_t)C3*KK];        /* Wqkv [hi|lo|hi] */
__device__ __nv_bfloat16 g_Wpc[(size_t)CC*KK];        /* Wproj permuted [hi|lo|hi] */

/* ---------------- PTX helpers --------------------------------------------- */
__device__ __forceinline__ uint32_t smem_u32(const void* p) {
    uint32_t a;
    asm("{ .reg .u64 t; cvta.to.shared.u64 t, %1; cvt.u32.u64 %0, t; }" : "=r"(a) : "l"(p));
    return a;
}
__device__ __forceinline__ void cpasync16(uint32_t s, const void* g) {
    asm volatile("cp.async.cg.shared.global [%0], [%1], 16;" :: "r"(s), "l"(g));
}
#define CP_COMMIT() asm volatile("cp.async.commit_group;" ::: "memory")
#define CP_WAIT2()  asm volatile("cp.async.wait_group 2;" ::: "memory")
#define CP_WAIT0()  asm volatile("cp.async.wait_group 0;" ::: "memory")

__device__ __forceinline__ void ldsm_x4(uint32_t* r, uint32_t addr) {
    asm volatile("ldmatrix.sync.aligned.m8n8.x4.shared.b16 {%0,%1,%2,%3}, [%4];"
                 : "=r"(r[0]), "=r"(r[1]), "=r"(r[2]), "=r"(r[3]) : "r"(addr));
}
__device__ __forceinline__ void ldsm_x2(uint32_t* r, uint32_t addr) {
    asm volatile("ldmatrix.sync.aligned.m8n8.x2.shared.b16 {%0,%1}, [%2];"
                 : "=r"(r[0]), "=r"(r[1]) : "r"(addr));
}
__device__ __forceinline__ void ldsm_x2_t(uint32_t* r, uint32_t addr) {
    asm volatile("ldmatrix.sync.aligned.m8n8.x2.trans.shared.b16 {%0,%1}, [%2];"
                 : "=r"(r[0]), "=r"(r[1]) : "r"(addr));
}
__device__ __forceinline__ void mma16816(float* c, const uint32_t* a, const uint32_t* b) {
    asm volatile("mma.sync.aligned.m16n8k16.row.col.f32.bf16.bf16.f32 "
                 "{%0,%1,%2,%3}, {%4,%5,%6,%7}, {%8,%9}, {%0,%1,%2,%3};"
                 : "+f"(c[0]), "+f"(c[1]), "+f"(c[2]), "+f"(c[3])
                 : "r"(a[0]), "r"(a[1]), "r"(a[2]), "r"(a[3]), "r"(b[0]), "r"(b[1]));
}
__device__ __forceinline__ uint32_t pk2(__nv_bfloat16 a, __nv_bfloat16 b) {
    __nv_bfloat162 t; t.x = a; t.y = b;
    return *(uint32_t*)&t;
}

/* ---------------- split conversions --------------------------------------- */
__global__ __launch_bounds__(256) void conv_A(const float* __restrict__ src) {
    int t = blockIdx.x * 256 + threadIdx.x;
    if (t >= MROWS * 96) return;
    int m = t / 96, q = t - m * 96;
    float4 v = *(const float4*)(src + (size_t)m * CC + q * 4);
    __nv_bfloat16 h0 = __float2bfloat16(v.x), h1 = __float2bfloat16(v.y);
    __nv_bfloat16 h2 = __float2bfloat16(v.z), h3 = __float2bfloat16(v.w);
    uint2 uh; uh.x = pk2(h0, h1); uh.y = pk2(h2, h3);
    uint2 ul;
    ul.x = pk2(__float2bfloat16(v.x - __bfloat162float(h0)),
               __float2bfloat16(v.y - __bfloat162float(h1)));
    ul.y = pk2(__float2bfloat16(v.z - __bfloat162float(h2)),
               __float2bfloat16(v.w - __bfloat162float(h3)));
    __nv_bfloat16* d = g_Xc + (size_t)m * AKW + q * 4;
    *(uint2*)d = uh;
    *(uint2*)(d + CC) = ul;
}
__global__ __launch_bounds__(256) void conv_Wq(const float* __restrict__ src) {
    int t = blockIdx.x * 256 + threadIdx.x;
    if (t >= C3 * 96) return;
    int o = t / 96, q = t - o * 96;
    float4 v = *(const float4*)(src + (size_t)o * CC + q * 4);
    __nv_bfloat16 h0 = __float2bfloat16(v.x), h1 = __float2bfloat16(v.y);
    __nv_bfloat16 h2 = __float2bfloat16(v.z), h3 = __float2bfloat16(v.w);
    uint2 uh; uh.x = pk2(h0, h1); uh.y = pk2(h2, h3);
    uint2 ul;
    ul.x = pk2(__float2bfloat16(v.x - __bfloat162float(h0)),
               __float2bfloat16(v.y - __bfloat162float(h1)));
    ul.y = pk2(__float2bfloat16(v.z - __bfloat162float(h2)),
               __float2bfloat16(v.w - __bfloat162float(h3)));
    __nv_bfloat16* d = g_Wqc + (size_t)o * KK + q * 4;
    *(uint2*)d = uh;
    *(uint2*)(d + CC) = ul;
    *(uint2*)(d + 2 * CC) = uh;
}
__global__ void conv_Wp(const float* __restrict__ src) {
    int o = blockIdx.x, c = threadIdx.x;
    int h = c >> 6, d = c & 63;
    float v = src[(size_t)o * CC + d * HH + h];
    __nv_bfloat16 hi = __float2bfloat16(v);
    __nv_bfloat16 lo = __float2bfloat16(v - __bfloat162float(hi));
    __nv_bfloat16* dst = g_Wpc + (size_t)o * KK;
    dst[c] = hi; dst[CC + c] = lo; dst[2 * CC + c] = hi;
}

/* ---------------- mma.sync GEMM mainloop (4-stage, 1 sync/iter) ----------- */
/* A stored 768-wide [hi|lo]; logical k-tile kt maps to A col:                */
/*   kt<24 -> (kt%12)*32 (hi), kt>=24 -> 384+(kt-24)*32 (lo).  B is 1152.     */
__device__ __forceinline__ int a_kcol(int kt) {
    return (kt < 24) ? (kt % 12) * 32 : 384 + (kt - 24) * 32;
}
__device__ __forceinline__ void prefetch_kt(const __nv_bfloat16* Ab,
                                            const __nv_bfloat16* Bb,
                                            uint32_t sm, int kt, int r0, int r1, int j0) {
    int st = kt & 3;
    int ak = a_kcol(kt), bk = kt * BK;
    uint32_t sa = sm + st * STAGE_BYTES;
    uint32_t sb = sm + B_REGION + st * STAGE_BYTES;
    cpasync16(sa + r0 * 80 + j0 * 16, Ab + (size_t)r0 * AKW + ak + j0 * 8);
    cpasync16(sa + r1 * 80 + j0 * 16, Ab + (size_t)r1 * AKW + ak + j0 * 8);
    cpasync16(sb + r0 * 80 + j0 * 16, Bb + (size_t)r0 * KK + bk + j0 * 8);
    cpasync16(sb + r1 * 80 + j0 * 16, Bb + (size_t)r1 * KK + bk + j0 * 8);
}
__device__ __forceinline__ void gemm_mainloop(const __nv_bfloat16* __restrict__ A,
                                              const __nv_bfloat16* __restrict__ Bm,
                                              int rowBase, int colBase,
                                              uint32_t sm, float acc[4][4][4]) {
    const int tid  = threadIdx.x;
    const int wid  = tid >> 5, lane = tid & 31;
    const int wr   = wid >> 2, wc = wid & 3;

    #pragma unroll
    for (int i = 0; i < 4; i++)
        #pragma unroll
        for (int j = 0; j < 4; j++)
            #pragma unroll
            for (int k = 0; k < 4; k++) acc[i][j][k] = 0.f;

    const __nv_bfloat16* Ab = A + (size_t)rowBase * AKW;
    const __nv_bfloat16* Bb = Bm + (size_t)colBase * KK;
    const int r0 = tid >> 2, j0 = tid & 3;
    const int r1 = r0 + 64;

    #pragma unroll
    for (int s = 0; s < 3; s++) {
        prefetch_kt(Ab, Bb, sm, s, r0, r1, j0);
        CP_COMMIT();
    }

    const uint32_t aoff = (uint32_t)((wr * 64 + (lane & 15)) * 80 + ((lane >> 4) & 1) * 16);
    const uint32_t boff = (uint32_t)((wc * 32 + (lane & 7)) * 80 + ((lane >> 3) & 1) * 16);

    #pragma unroll 1
    for (int kt = 0; kt < NKT; kt++) {
        CP_WAIT2();
        __syncthreads();
        if (kt + 3 < NKT) prefetch_kt(Ab, Bb, sm, kt + 3, r0, r1, j0);
        CP_COMMIT();

        const int st = kt & 3;
        const uint32_t aBase = sm + st * STAGE_BYTES + aoff;
        const uint32_t bBase = sm + B_REGION + st * STAGE_BYTES + boff;
        #pragma unroll
        for (int ks = 0; ks < 2; ks++) {
            uint32_t af[4][4], bf[4][2];
            #pragma unroll
            for (int i = 0; i < 4; i++)
                ldsm_x4(af[i], aBase + (uint32_t)(i * 16 * 80 + ks * 32));
            #pragma unroll
            for (int j = 0; j < 4; j++)
                ldsm_x2(bf[j], bBase + (uint32_t)(j * 8 * 80 + ks * 32));
            #pragma unroll
            for (int i = 0; i < 4; i++)
                #pragma unroll
                for (int j = 0; j < 4; j++)
                    mma16816(acc[i][j], af[i], bf[j]);
        }
    }
    CP_WAIT0();
    __syncthreads();
}

__device__ __forceinline__ void acc_to_smem(float* eps, float acc[4][4][4]) {
    const int tid = threadIdx.x, wid = tid >> 5, lane = tid & 31;
    const int wr = wid >> 2, wc = wid & 3;
    const int rl = lane >> 2, cl = 2 * (lane & 3);
    #pragma unroll
    for (int i = 0; i < 4; i++) {
        #pragma unroll
        for (int j = 0; j < 4; j++) {
            int r = wr * 64 + i * 16 + rl;
            int c = wc * 32 + j * 8 + cl;
            eps[r * 132 + c]       = acc[i][j][0];
            eps[r * 132 + c + 1]   = acc[i][j][1];
            eps[(r + 8) * 132 + c] = acc[i][j][2];
            eps[(r + 8) * 132 + c + 1] = acc[i][j][3];
        }
    }
    __syncthreads();
}

/* ---------------- QKV GEMM kernel ------------------------------------------ */
__global__ __launch_bounds__(256) void qkv_mma(const float* __restrict__ bias) {
    extern __shared__ char dynsm[];
    uint32_t sm = smem_u32(dynsm);
    const int colBase = blockIdx.x * 128;
    const int rowBase = blockIdx.y * 128;

    float acc[4][4][4];
    gemm_mainloop(g_Xc, g_Wqc, rowBase, colBase, sm, acc);
    float* eps = (float*)dynsm;
    acc_to_smem(eps, acc);

    const int tid = threadIdx.x, w = tid >> 5, lane = tid & 31;
    const int s  = colBase / CC;
    const int hb = (colBase - s * CC) >> 6;
    const float mul = (s == 0) ? QK_SCALE : 1.0f;
    __nv_bfloat16* dhi = (s == 0) ? g_Qh : (s == 1) ? g_Kh : g_Vh;
    __nv_bfloat16* dlo = (s == 0) ? g_Ql : (s == 1) ? g_Kl : g_Vl;
    #pragma unroll
    for (int it = 0; it < 16; it++) {
        int run = (it * 8 + w) * 2 + (lane >> 4);
        int row = run >> 1, hh = run & 1, j = lane & 15;
        int m = rowBase + row;
        int bt = m / NP, n = m - bt * NP;
        float4 v = *(float4*)(eps + row * 132 + hh * 64 + j * 4);
        float4 bv = *(const float4*)(bias + colBase + hh * 64 + j * 4);
        v.x = (v.x + bv.x) * mul; v.y = (v.y + bv.y) * mul;
        v.z = (v.z + bv.z) * mul; v.w = (v.w + bv.w) * mul;
        __nv_bfloat16 h0 = __float2bfloat16(v.x), h1 = __float2bfloat16(v.y);
        __nv_bfloat16 h2 = __float2bfloat16(v.z), h3 = __float2bfloat16(v.w);
        uint2 uh; uh.x = pk2(h0, h1); uh.y = pk2(h2, h3);
        uint2 ul;
        ul.x = pk2(__float2bfloat16(v.x - __bfloat162float(h0)),
                   __float2bfloat16(v.y - __bfloat162float(h1)));
        ul.y = pk2(__float2bfloat16(v.z - __bfloat162float(h2)),
                   __float2bfloat16(v.w - __bfloat162float(h3)));
        size_t off = ((size_t)(bt * HH + hb + hh) * NP + n) * HD + j * 4;
        *(uint2*)(dhi + off) = uh;
        *(uint2*)(dlo + off) = ul;
    }
}

/* ---------------- proj GEMM kernel ----------------------------------------- */
__global__ __launch_bounds__(256) void proj_mma(const float* __restrict__ bias,
                                                float* __restrict__ out) {
    extern __shared__ char dynsm[];
    uint32_t sm = smem_u32(dynsm);
    const int colBase = blockIdx.x * 128;
    const int rowBase = blockIdx.y * 128;

    float acc[4][4][4];
    gemm_mainloop(g_Ac, g_Wpc, rowBase, colBase, sm, acc);
    float* eps = (float*)dynsm;
    acc_to_smem(eps, acc);

    const int tid = threadIdx.x, w = tid >> 5, lane = tid & 31;
    float4 bv = *(const float4*)(bias + colBase + lane * 4);
    #pragma unroll
    for (int it = 0; it < 16; it++) {
        int row = it * 8 + w;
        int m = rowBase + row;
        float4 v = *(float4*)(eps + row * 132 + lane * 4);
        v.x += bv.x; v.y += bv.y; v.z += bv.z; v.w += bv.w;
        *(float4*)(out + (size_t)m * CC + colBase + lane * 4) = v;
    }
}

/* ---------------- attention via mma.sync ----------------------------------- */
template<int NT>
__device__ __forceinline__ void attn_chunk(uint32_t sb, int lane, int cbase,
                                           const uint32_t qh[4][4], const uint32_t ql[4][4],
                                           float o[8][4], float& lp0, float& lp1) {
    float s[NT][4];
    #pragma unroll
    for (int t = 0; t < NT; t++)
        #pragma unroll
        for (int e = 0; e < 4; e++) s[t][e] = 0.f;

    /* --- QK --- */
    #pragma unroll
    for (int t = 0; t < NT; t++) {
        #pragma unroll
        for (int ks = 0; ks < 4; ks++) {
            uint32_t bh[2], bl[2];
            uint32_t off = (uint32_t)((cbase + t * 8 + (lane & 7)) * KSTRB
                                      + ks * 32 + ((lane >> 3) & 1) * 16);
            ldsm_x2(bh, sb + SM_KH + off);
            ldsm_x2(bl, sb + SM_KL + off);
            mma16816(s[t], qh[ks], bh);
            mma16816(s[t], qh[ks], bl);
            mma16816(s[t], ql[ks], bh);
        }
    }

    /* --- exp + mask + pack P --- */
    uint32_t phi[NT/2][4], plo[NT/2][4];
    #pragma unroll
    for (int t = 0; t < NT; t++) {
        int c0 = cbase + t * 8 + 2 * (lane & 3);
        float p0 = (c0     < NP) ? __expf(s[t][0]) : 0.f;
        float p1 = (c0 + 1 < NP) ? __expf(s[t][1]) : 0.f;
        float p2 = (c0     < NP) ? __expf(s[t][2]) : 0.f;
        float p3 = (c0 + 1 < NP) ? __expf(s[t][3]) : 0.f;
        lp0 += p0 + p1;
        lp1 += p2 + p3;
        __nv_bfloat16 h0 = __float2bfloat16(p0), h1 = __float2bfloat16(p1);
        __nv_bfloat16 h2 = __float2bfloat16(p2), h3 = __float2bfloat16(p3);
        int j = t >> 1, oreg = (t & 1) * 2;
        phi[j][oreg]     = pk2(h0, h1);
        phi[j][oreg + 1] = pk2(h2, h3);
        plo[j][oreg]     = pk2(__float2bfloat16(p0 - __bfloat162float(h0)),
                               __float2bfloat16(p1 - __bfloat162float(h1)));
        plo[j][oreg + 1] = pk2(__float2bfloat16(p2 - __bfloat162float(h2)),
                               __float2bfloat16(p3 - __bfloat162float(h3)));
    }

    /* --- PV: b-frags via ldmatrix.trans on V rows [n][d] --- */
    #pragma unroll
    for (int j = 0; j < NT / 2; j++) {
        #pragma unroll
        for (int nd = 0; nd < 8; nd++) {
            uint32_t bh[2], bl[2];
            uint32_t off = (uint32_t)((cbase + j * 16 + (lane & 15)) * KSTRB + nd * 16);
            ldsm_x2_t(bh, sb + SM_VH + off);
            ldsm_x2_t(bl, sb + SM_VL + off);
            mma16816(o[nd], phi[j], bh);
            mma16816(o[nd], phi[j], bl);
            mma16816(o[nd], plo[j], bh);
        }
    }
}

__global__ __launch_bounds__(416, 1) void attn_mma() {
    extern __shared__ char smc[];
    uint32_t sb = smem_u32(smc);
    const int bx = blockIdx.x;                 /* bt*6 + h */
    const int tid = threadIdx.x, wid = tid >> 5, lane = tid & 31;

    for (int i = tid; i < ATT_SMEM / 16; i += 416)
        ((uint4*)smc)[i] = make_uint4(0, 0, 0, 0);
    __syncthreads();

    const size_t base = (size_t)bx * NP * HD;
    for (int i = tid; i < NP * 8; i += 416) {
        int r = i >> 3, j = i & 7;
        uint32_t doff = (uint32_t)(r * KSTRB + j * 16);
        *(uint4*)(smc + SM_QH + doff) = ((const uint4*)(g_Qh + base))[i];
        *(uint4*)(smc + SM_QL + doff) = ((const uint4*)(g_Ql + base))[i];
        *(uint4*)(smc + SM_KH + doff) = ((const uint4*)(g_Kh + base))[i];
        *(uint4*)(smc + SM_KL + doff) = ((const uint4*)(g_Kl + base))[i];
        *(uint4*)(smc + SM_VH + doff) = ((const uint4*)(g_Vh + base))[i];
        *(uint4*)(smc + SM_VL + doff) = ((const uint4*)(g_Vl + base))[i];
    }
    __syncthreads();

    uint32_t qh[4][4], ql[4][4];
    {
        uint32_t qoff = (uint32_t)((wid * 16 + (lane & 15)) * KSTRB + ((lane >> 4) & 1) * 16);
        #pragma unroll
        for (int ks = 0; ks < 4; ks++) {
            ldsm_x4(qh[ks], sb + SM_QH + qoff + ks * 32);
            ldsm_x4(ql[ks], sb + SM_QL + qoff + ks * 32);
        }
    }

    float o[8][4];
    #pragma unroll
    for (int nd = 0; nd < 8; nd++)
        #pragma unroll
        for (int e = 0; e < 4; e++) o[nd][e] = 0.f;
    float lp0 = 0.f, lp1 = 0.f;

    attn_chunk<14>(sb, lane, 0,   qh, ql, o, lp0, lp1);
    attn_chunk<12>(sb, lane, 112, qh, ql, o, lp0, lp1);

    lp0 += __shfl_xor_sync(0xFFFFFFFFu, lp0, 1);
    lp0 += __shfl_xor_sync(0xFFFFFFFFu, lp0, 2);
    lp1 += __shfl_xor_sync(0xFFFFFFFFu, lp1, 1);
    lp1 += __shfl_xor_sync(0xFFFFFFFFu, lp1, 2);
    const float inv0 = 1.0f / lp0, inv1 = 1.0f / lp1;

    const int bt = bx / HH, h = bx - bt * HH;
    const int r0 = wid * 16 + (lane >> 2);
    const int cl = 2 * (lane & 3);
    #pragma unroll
    for (int nd = 0; nd < 8; nd++) {
        int col = h * HD + nd * 8 + cl;
        if (r0 < NP) {
            float v0 = o[nd][0] * inv0, v1 = o[nd][1] * inv0;
            __nv_bfloat16 a0 = __float2bfloat16(v0), a1 = __float2bfloat16(v1);
            size_t ro = ((size_t)bt * NP + r0) * AKW + col;
            *(uint32_t*)(g_Ac + ro)      = pk2(a0, a1);
            *(uint32_t*)(g_Ac + ro + CC) = pk2(__float2bfloat16(v0 - __bfloat162float(a0)),
                                               __float2bfloat16(v1 - __bfloat162float(a1)));
        }
        if (r0 + 8 < NP) {
            float v2 = o[nd][2] * inv1, v3 = o[nd][3] * inv1;
            __nv_bfloat16 a2 = __float2bfloat16(v2), a3 = __float2bfloat16(v3);
            size_t ro = ((size_t)bt * NP + r0 + 8) * AKW + col;
            *(uint32_t*)(g_Ac + ro)      = pk2(a2, a3);
            *(uint32_t*)(g_Ac + ro + CC) = pk2(__float2bfloat16(v2 - __bfloat162float(a2)),
                                               __float2bfloat16(v3 - __bfloat162float(a3)));
        }
    }
}

/* ---------------- launch --------------------------------------------------- */
extern "C" void kernel_launch(void* const* d_in, const int* in_sizes, int n_in,
                              void* d_out, int out_size) {
    const float* x     = (const float*)d_in[0];
    const float* Wqkv  = (const float*)d_in[1];
    const float* bqkv  = (const float*)d_in[2];
    const float* Wproj = (const float*)d_in[3];
    const float* bproj = (const float*)d_in[4];
    float* out = (float*)d_out;

    cudaFuncSetAttribute(attn_mma, cudaFuncAttributeMaxDynamicSharedMemorySize, ATT_SMEM);
    cudaFuncSetAttribute(qkv_mma,  cudaFuncAttributeMaxDynamicSharedMemorySize, SMEM_SZ);
    cudaFuncSetAttribute(proj_mma, cudaFuncAttributeMaxDynamicSharedMemorySize, SMEM_SZ);

    conv_A <<<(MROWS * 96 + 255) / 256, 256>>>(x);
    conv_Wq<<<(C3 * 96 + 255) / 256, 256>>>(Wqkv);
    conv_Wp<<<CC, CC>>>(Wproj);
    qkv_mma<<<dim3(C3 / 128, MROWS / 128), 256, SMEM_SZ>>>(bqkv);
    attn_mma<<<NBH, 416, ATT_SMEM>>>();
    proj_mma<<<dim3(CC / 128, MROWS / 128), 256, SMEM_SZ>>>(bproj, out);
}

// round 8
// speedup vs baseline: 2.5758x; 1.1504x over previous
#include <cuda_runtime.h>
#include <cuda_bf16.h>
#include <math_constants.h>
#include <cstdint>

#define BB 8
#define TT 64
#define NP 196
#define HH 6
#define HD 64
#define CC 384
#define C3 1152
#define KK 1152              /* logical split-K: [hi|hi|lo] x [hi|lo|hi] */
#define AKW 768              /* stored A width: [hi|lo], hi reused for k<768 */
#define BT (BB*TT)           /* 512 */
#define MROWS (BT*NP)        /* 100352 */
#define NBH (BT*HH)          /* 3072 */
#define QK_SCALE 0.125f

#define BK 64
#define NKT (KK/BK)          /* 18 k-tiles */
#define STRB 144             /* smem row stride: 64 bf16 data + 8 pad */
#define STAGE_BYTES (128*STRB)          /* 18432 */
#define B_REGION (3*STAGE_BYTES)        /* A: 3 stages, then B: 3 stages */
#define SMEM_SZ (6*STAGE_BYTES)         /* 110592; epilogue (67584) reuses */

/* attention smem: K hi/lo + V hi/lo; 196 rows each, Vl padded to 208 */
#define KSTRB 144
#define SM_KH 0
#define SM_KL 28224          /* 196*144 */
#define SM_VH 56448
#define SM_VL 84672
#define ATT_SMEM 114624      /* 84672 + 208*144 */

/* ---------------- scratch ------------------------------------------------- */
__device__ __nv_bfloat16 g_Qh[(size_t)NBH*NP*HD];     /* [bh][n][d] hi */
__device__ __nv_bfloat16 g_Ql[(size_t)NBH*NP*HD];
__device__ __nv_bfloat16 g_Kh[(size_t)NBH*NP*HD];
__device__ __nv_bfloat16 g_Kl[(size_t)NBH*NP*HD];
__device__ __nv_bfloat16 g_Vh[(size_t)NBH*NP*HD];
__device__ __nv_bfloat16 g_Vl[(size_t)NBH*NP*HD];
__device__ __nv_bfloat16 g_Xc[(size_t)MROWS*AKW];     /* X [hi|lo] */
__device__ __nv_bfloat16 g_Ac[(size_t)MROWS*AKW];     /* attn out [hi|lo] */
__device__ __nv_bfloat16 g_Wqc[(size_t)C3*KK];        /* Wqkv [hi|lo|hi] */
__device__ __nv_bfloat16 g_Wpc[(size_t)CC*KK];        /* Wproj permuted [hi|lo|hi] */

/* ---------------- PTX helpers --------------------------------------------- */
__device__ __forceinline__ uint32_t smem_u32(const void* p) {
    uint32_t a;
    asm("{ .reg .u64 t; cvta.to.shared.u64 t, %1; cvt.u32.u64 %0, t; }" : "=r"(a) : "l"(p));
    return a;
}
__device__ __forceinline__ void cpasync16(uint32_t s, const void* g) {
    asm volatile("cp.async.cg.shared.global [%0], [%1], 16;" :: "r"(s), "l"(g));
}
#define CP_COMMIT() asm volatile("cp.async.commit_group;" ::: "memory")
#define CP_WAIT1()  asm volatile("cp.async.wait_group 1;" ::: "memory")
#define CP_WAIT0()  asm volatile("cp.async.wait_group 0;" ::: "memory")

__device__ __forceinline__ void ldsm_x4(uint32_t* r, uint32_t addr) {
    asm volatile("ldmatrix.sync.aligned.m8n8.x4.shared.b16 {%0,%1,%2,%3}, [%4];"
                 : "=r"(r[0]), "=r"(r[1]), "=r"(r[2]), "=r"(r[3]) : "r"(addr));
}
__device__ __forceinline__ void ldsm_x2(uint32_t* r, uint32_t addr) {
    asm volatile("ldmatrix.sync.aligned.m8n8.x2.shared.b16 {%0,%1}, [%2];"
                 : "=r"(r[0]), "=r"(r[1]) : "r"(addr));
}
__device__ __forceinline__ void ldsm_x2_t(uint32_t* r, uint32_t addr) {
    asm volatile("ldmatrix.sync.aligned.m8n8.x2.trans.shared.b16 {%0,%1}, [%2];"
                 : "=r"(r[0]), "=r"(r[1]) : "r"(addr));
}
__device__ __forceinline__ void mma16816(float* c, const uint32_t* a, const uint32_t* b) {
    asm volatile("mma.sync.aligned.m16n8k16.row.col.f32.bf16.bf16.f32 "
                 "{%0,%1,%2,%3}, {%4,%5,%6,%7}, {%8,%9}, {%0,%1,%2,%3};"
                 : "+f"(c[0]), "+f"(c[1]), "+f"(c[2]), "+f"(c[3])
                 : "r"(a[0]), "r"(a[1]), "r"(a[2]), "r"(a[3]), "r"(b[0]), "r"(b[1]));
}
__device__ __forceinline__ uint32_t pk2(__nv_bfloat16 a, __nv_bfloat16 b) {
    __nv_bfloat162 t; t.x = a; t.y = b;
    return *(uint32_t*)&t;
}

/* ---------------- split conversions --------------------------------------- */
__global__ __launch_bounds__(256) void conv_A(const float* __restrict__ src) {
    int t = blockIdx.x * 256 + threadIdx.x;
    if (t >= MROWS * 96) return;
    int m = t / 96, q = t - m * 96;
    float4 v = *(const float4*)(src + (size_t)m * CC + q * 4);
    __nv_bfloat16 h0 = __float2bfloat16(v.x), h1 = __float2bfloat16(v.y);
    __nv_bfloat16 h2 = __float2bfloat16(v.z), h3 = __float2bfloat16(v.w);
    uint2 uh; uh.x = pk2(h0, h1); uh.y = pk2(h2, h3);
    uint2 ul;
    ul.x = pk2(__float2bfloat16(v.x - __bfloat162float(h0)),
               __float2bfloat16(v.y - __bfloat162float(h1)));
    ul.y = pk2(__float2bfloat16(v.z - __bfloat162float(h2)),
               __float2bfloat16(v.w - __bfloat162float(h3)));
    __nv_bfloat16* d = g_Xc + (size_t)m * AKW + q * 4;
    *(uint2*)d = uh;
    *(uint2*)(d + CC) = ul;
}
__global__ __launch_bounds__(256) void conv_Wq(const float* __restrict__ src) {
    int t = blockIdx.x * 256 + threadIdx.x;
    if (t >= C3 * 96) return;
    int o = t / 96, q = t - o * 96;
    float4 v = *(const float4*)(src + (size_t)o * CC + q * 4);
    __nv_bfloat16 h0 = __float2bfloat16(v.x), h1 = __float2bfloat16(v.y);
    __nv_bfloat16 h2 = __float2bfloat16(v.z), h3 = __float2bfloat16(v.w);
    uint2 uh; uh.x = pk2(h0, h1); uh.y = pk2(h2, h3);
    uint2 ul;
    ul.x = pk2(__float2bfloat16(v.x - __bfloat162float(h0)),
               __float2bfloat16(v.y - __bfloat162float(h1)));
    ul.y = pk2(__float2bfloat16(v.z - __bfloat162float(h2)),
               __float2bfloat16(v.w - __bfloat162float(h3)));
    __nv_bfloat16* d = g_Wqc + (size_t)o * KK + q * 4;
    *(uint2*)d = uh;
    *(uint2*)(d + CC) = ul;
    *(uint2*)(d + 2 * CC) = uh;
}
__global__ void conv_Wp(const float* __restrict__ src) {
    int o = blockIdx.x, c = threadIdx.x;
    int h = c >> 6, d = c & 63;
    float v = src[(size_t)o * CC + d * HH + h];
    __nv_bfloat16 hi = __float2bfloat16(v);
    __nv_bfloat16 lo = __float2bfloat16(v - __bfloat162float(hi));
    __nv_bfloat16* dst = g_Wpc + (size_t)o * KK;
    dst[c] = hi; dst[CC + c] = lo; dst[2 * CC + c] = hi;
}

/* ---------------- mma.sync GEMM mainloop (BK=64, 3-stage) ------------------ */
/* A stored 768-wide [hi|lo]; logical 64-wide k-tile kt -> A col:             */
/*   kt<12 -> (kt%6)*64 (hi), kt>=12 -> 384+(kt-12)*64 (lo).                  */
__device__ __forceinline__ int a_kcol(int kt) {
    return (kt < 12) ? (kt % 6) * 64 : 384 + (kt - 12) * 64;
}
__device__ __forceinline__ void prefetch_kt(const __nv_bfloat16* Ab,
                                            const __nv_bfloat16* Bb,
                                            uint32_t sm, int kt, int tid) {
    const int st = kt % 3;
    const int ak = a_kcol(kt), bk = kt * BK;
    const uint32_t sa = sm + st * STAGE_BYTES;
    const uint32_t sb = sm + B_REGION + st * STAGE_BYTES;
    #pragma unroll
    for (int it = 0; it < 4; it++) {
        int idx = it * 256 + tid;
        int r = idx >> 3, jj = idx & 7;
        cpasync16(sa + r * STRB + jj * 16, Ab + (size_t)r * AKW + ak + jj * 8);
        cpasync16(sb + r * STRB + jj * 16, Bb + (size_t)r * KK + bk + jj * 8);
    }
}
__device__ __forceinline__ void gemm_mainloop(const __nv_bfloat16* __restrict__ A,
                                              const __nv_bfloat16* __restrict__ Bm,
                                              int rowBase, int colBase,
                                              uint32_t sm, float acc[4][4][4]) {
    const int tid  = threadIdx.x;
    const int wid  = tid >> 5, lane = tid & 31;
    const int wr   = wid >> 2, wc = wid & 3;

    #pragma unroll
    for (int i = 0; i < 4; i++)
        #pragma unroll
        for (int j = 0; j < 4; j++)
            #pragma unroll
            for (int k = 0; k < 4; k++) acc[i][j][k] = 0.f;

    const __nv_bfloat16* Ab = A + (size_t)rowBase * AKW;
    const __nv_bfloat16* Bb = Bm + (size_t)colBase * KK;

    prefetch_kt(Ab, Bb, sm, 0, tid); CP_COMMIT();
    prefetch_kt(Ab, Bb, sm, 1, tid); CP_COMMIT();

    const uint32_t aoff = (uint32_t)((wr * 64 + (lane & 15)) * STRB + ((lane >> 4) & 1) * 16);
    const uint32_t boff = (uint32_t)((wc * 32 + (lane & 7) + ((lane >> 4) & 1) * 8) * STRB
                                     + ((lane >> 3) & 1) * 16);

    #pragma unroll 1
    for (int kt = 0; kt < NKT; kt++) {
        CP_WAIT1();
        __syncthreads();
        if (kt + 2 < NKT) prefetch_kt(Ab, Bb, sm, kt + 2, tid);
        CP_COMMIT();

        const int st = kt % 3;
        const uint32_t aBase = sm + st * STAGE_BYTES + aoff;
        const uint32_t bBase = sm + B_REGION + st * STAGE_BYTES + boff;
        #pragma unroll
        for (int ks = 0; ks < 4; ks++) {
            uint32_t af[4][4], bf[2][4];
            #pragma unroll
            for (int i = 0; i < 4; i++)
                ldsm_x4(af[i], aBase + (uint32_t)(i * 16 * STRB + ks * 32));
            #pragma unroll
            for (int jj = 0; jj < 2; jj++)
                ldsm_x4(bf[jj], bBase + (uint32_t)(jj * 16 * STRB + ks * 32));
            #pragma unroll
            for (int i = 0; i < 4; i++) {
                mma16816(acc[i][0], af[i], bf[0]);
                mma16816(acc[i][1], af[i], bf[0] + 2);
                mma16816(acc[i][2], af[i], bf[1]);
                mma16816(acc[i][3], af[i], bf[1] + 2);
            }
        }
    }
    CP_WAIT0();
    __syncthreads();
}

__device__ __forceinline__ void acc_to_smem(float* eps, float acc[4][4][4]) {
    const int tid = threadIdx.x, wid = tid >> 5, lane = tid & 31;
    const int wr = wid >> 2, wc = wid & 3;
    const int rl = lane >> 2, cl = 2 * (lane & 3);
    #pragma unroll
    for (int i = 0; i < 4; i++) {
        #pragma unroll
        for (int j = 0; j < 4; j++) {
            int r = wr * 64 + i * 16 + rl;
            int c = wc * 32 + j * 8 + cl;
            eps[r * 132 + c]       = acc[i][j][0];
            eps[r * 132 + c + 1]   = acc[i][j][1];
            eps[(r + 8) * 132 + c] = acc[i][j][2];
            eps[(r + 8) * 132 + c + 1] = acc[i][j][3];
        }
    }
    __syncthreads();
}

/* ---------------- QKV GEMM kernel ------------------------------------------ */
__global__ __launch_bounds__(256) void qkv_mma(const float* __restrict__ bias) {
    extern __shared__ char dynsm[];
    uint32_t sm = smem_u32(dynsm);
    const int colBase = blockIdx.x * 128;
    const int rowBase = blockIdx.y * 128;

    float acc[4][4][4];
    gemm_mainloop(g_Xc, g_Wqc, rowBase, colBase, sm, acc);
    float* eps = (float*)dynsm;
    acc_to_smem(eps, acc);

    const int tid = threadIdx.x, w = tid >> 5, lane = tid & 31;
    const int s  = colBase / CC;
    const int hb = (colBase - s * CC) >> 6;
    const float mul = (s == 0) ? QK_SCALE : 1.0f;
    __nv_bfloat16* dhi = (s == 0) ? g_Qh : (s == 1) ? g_Kh : g_Vh;
    __nv_bfloat16* dlo = (s == 0) ? g_Ql : (s == 1) ? g_Kl : g_Vl;
    #pragma unroll
    for (int it = 0; it < 16; it++) {
        int run = (it * 8 + w) * 2 + (lane >> 4);
        int row = run >> 1, hh = run & 1, j = lane & 15;
        int m = rowBase + row;
        int bt = m / NP, n = m - bt * NP;
        float4 v = *(float4*)(eps + row * 132 + hh * 64 + j * 4);
        float4 bv = *(const float4*)(bias + colBase + hh * 64 + j * 4);
        v.x = (v.x + bv.x) * mul; v.y = (v.y + bv.y) * mul;
        v.z = (v.z + bv.z) * mul; v.w = (v.w + bv.w) * mul;
        __nv_bfloat16 h0 = __float2bfloat16(v.x), h1 = __float2bfloat16(v.y);
        __nv_bfloat16 h2 = __float2bfloat16(v.z), h3 = __float2bfloat16(v.w);
        uint2 uh; uh.x = pk2(h0, h1); uh.y = pk2(h2, h3);
        uint2 ul;
        ul.x = pk2(__float2bfloat16(v.x - __bfloat162float(h0)),
                   __float2bfloat16(v.y - __bfloat162float(h1)));
        ul.y = pk2(__float2bfloat16(v.z - __bfloat162float(h2)),
                   __float2bfloat16(v.w - __bfloat162float(h3)));
        size_t off = ((size_t)(bt * HH + hb + hh) * NP + n) * HD + j * 4;
        *(uint2*)(dhi + off) = uh;
        *(uint2*)(dlo + off) = ul;
    }
}

/* ---------------- proj GEMM kernel ----------------------------------------- */
__global__ __launch_bounds__(256) void proj_mma(const float* __restrict__ bias,
                                                float* __restrict__ out) {
    extern __shared__ char dynsm[];
    uint32_t sm = smem_u32(dynsm);
    const int colBase = blockIdx.x * 128;
    const int rowBase = blockIdx.y * 128;

    float acc[4][4][4];
    gemm_mainloop(g_Ac, g_Wpc, rowBase, colBase, sm, acc);
    float* eps = (float*)dynsm;
    acc_to_smem(eps, acc);

    const int tid = threadIdx.x, w = tid >> 5, lane = tid & 31;
    float4 bv = *(const float4*)(bias + colBase + lane * 4);
    #pragma unroll
    for (int it = 0; it < 16; it++) {
        int row = it * 8 + w;
        int m = rowBase + row;
        float4 v = *(float4*)(eps + row * 132 + lane * 4);
        v.x += bv.x; v.y += bv.y; v.z += bv.z; v.w += bv.w;
        *(float4*)(out + (size_t)m * CC + colBase + lane * 4) = v;
    }
}

/* ---------------- attention via mma.sync ----------------------------------- */
template<int NT>
__device__ __forceinline__ void attn_chunk(uint32_t sb, int lane, int cbase,
                                           const uint32_t qh[4][4], const uint32_t ql[4][4],
                                           float o[8][4], float& lp0, float& lp1) {
    float s[NT][4];
    #pragma unroll
    for (int t = 0; t < NT; t++)
        #pragma unroll
        for (int e = 0; e < 4; e++) s[t][e] = 0.f;

    /* --- QK --- */
    #pragma unroll
    for (int t = 0; t < NT; t++) {
        #pragma unroll
        for (int ks = 0; ks < 4; ks++) {
            uint32_t bh[2], bl[2];
            uint32_t off = (uint32_t)((cbase + t * 8 + (lane & 7)) * KSTRB
                                      + ks * 32 + ((lane >> 3) & 1) * 16);
            ldsm_x2(bh, sb + SM_KH + off);
            ldsm_x2(bl, sb + SM_KL + off);
            mma16816(s[t], qh[ks], bh);
            mma16816(s[t], qh[ks], bl);
            mma16816(s[t], ql[ks], bh);
        }
    }

    /* --- exp + mask + pack P --- */
    uint32_t phi[NT/2][4], plo[NT/2][4];
    #pragma unroll
    for (int t = 0; t < NT; t++) {
        int c0 = cbase + t * 8 + 2 * (lane & 3);
        float p0 = (c0     < NP) ? __expf(s[t][0]) : 0.f;
        float p1 = (c0 + 1 < NP) ? __expf(s[t][1]) : 0.f;
        float p2 = (c0     < NP) ? __expf(s[t][2]) : 0.f;
        float p3 = (c0 + 1 < NP) ? __expf(s[t][3]) : 0.f;
        lp0 += p0 + p1;
        lp1 += p2 + p3;
        __nv_bfloat16 h0 = __float2bfloat16(p0), h1 = __float2bfloat16(p1);
        __nv_bfloat16 h2 = __float2bfloat16(p2), h3 = __float2bfloat16(p3);
        int j = t >> 1, oreg = (t & 1) * 2;
        phi[j][oreg]     = pk2(h0, h1);
        phi[j][oreg + 1] = pk2(h2, h3);
        plo[j][oreg]     = pk2(__float2bfloat16(p0 - __bfloat162float(h0)),
                               __float2bfloat16(p1 - __bfloat162float(h1)));
        plo[j][oreg + 1] = pk2(__float2bfloat16(p2 - __bfloat162float(h2)),
                               __float2bfloat16(p3 - __bfloat162float(h3)));
    }

    /* --- PV: b-frags via ldmatrix.trans on V rows [n][d] --- */
    #pragma unroll
    for (int j = 0; j < NT / 2; j++) {
        #pragma unroll
        for (int nd = 0; nd < 8; nd++) {
            uint32_t bh[2], bl[2];
            uint32_t off = (uint32_t)((cbase + j * 16 + (lane & 15)) * KSTRB + nd * 16);
            ldsm_x2_t(bh, sb + SM_VH + off);
            ldsm_x2_t(bl, sb + SM_VL + off);
            mma16816(o[nd], phi[j], bh);
            mma16816(o[nd], phi[j], bl);
            mma16816(o[nd], plo[j], bh);
        }
    }
}

__global__ __launch_bounds__(416, 1) void attn_mma() {
    extern __shared__ char smc[];
    uint32_t sb = smem_u32(smc);
    const int bx = blockIdx.x;                 /* bt*6 + h */
    const int tid = threadIdx.x, wid = tid >> 5, lane = tid & 31;

    const size_t base = (size_t)bx * NP * HD;
    /* K/V copy-in: 196 rows x 8 uint4 per array (no zero-fill; garbage pad
       rows are masked: K pad -> p=0; V pad reads land in next region (finite)
       or the zeroed Vl tail below) */
    for (int i = tid; i < NP * 8; i += 416) {
        int r = i >> 3, j = i & 7;
        uint32_t doff = (uint32_t)(r * KSTRB + j * 16);
        *(uint4*)(smc + SM_KH + doff) = ((const uint4*)(g_Kh + base))[i];
        *(uint4*)(smc + SM_KL + doff) = ((const uint4*)(g_Kl + base))[i];
        *(uint4*)(smc + SM_VH + doff) = ((const uint4*)(g_Vh + base))[i];
        *(uint4*)(smc + SM_VL + doff) = ((const uint4*)(g_Vl + base))[i];
    }
    /* zero Vl pad rows 196-207 (12*144B = 108 uint4) to avoid NaN*0 in PV */
    if (tid < 108)
        *(uint4*)(smc + SM_VL + 196 * KSTRB + tid * 16) = make_uint4(0, 0, 0, 0);

    /* Q fragments straight from gmem (row-clamped; pad rows discarded) */
    uint32_t qh[4][4], ql[4][4];
    {
        const uint32_t* qhp = (const uint32_t*)(g_Qh + base);
        const uint32_t* qlp = (const uint32_t*)(g_Ql + base);
        int r  = wid * 16 + (lane >> 2);
        int r2 = r + 8;
        int ra  = (r  < NP) ? r  : NP - 1;
        int r2a = (r2 < NP) ? r2 : NP - 1;
        int c = lane & 3;
        #pragma unroll
        for (int ks = 0; ks < 4; ks++) {
            qh[ks][0] = qhp[ra  * 32 + ks * 8 + c];
            qh[ks][1] = qhp[r2a * 32 + ks * 8 + c];
            qh[ks][2] = qhp[ra  * 32 + ks * 8 + 4 + c];
            qh[ks][3] = qhp[r2a * 32 + ks * 8 + 4 + c];
            ql[ks][0] = qlp[ra  * 32 + ks * 8 + c];
            ql[ks][1] = qlp[r2a * 32 + ks * 8 + c];
            ql[ks][2] = qlp[ra  * 32 + ks * 8 + 4 + c];
            ql[ks][3] = qlp[r2a * 32 + ks * 8 + 4 + c];
        }
    }
    __syncthreads();

    float o[8][4];
    #pragma unroll
    for (int nd = 0; nd < 8; nd++)
        #pragma unroll
        for (int e = 0; e < 4; e++) o[nd][e] = 0.f;
    float lp0 = 0.f, lp1 = 0.f;

    attn_chunk<14>(sb, lane, 0,   qh, ql, o, lp0, lp1);
    attn_chunk<12>(sb, lane, 112, qh, ql, o, lp0, lp1);

    lp0 += __shfl_xor_sync(0xFFFFFFFFu, lp0, 1);
    lp0 += __shfl_xor_sync(0xFFFFFFFFu, lp0, 2);
    lp1 += __shfl_xor_sync(0xFFFFFFFFu, lp1, 1);
    lp1 += __shfl_xor_sync(0xFFFFFFFFu, lp1, 2);
    const float inv0 = 1.0f / lp0, inv1 = 1.0f / lp1;

    const int bt = bx / HH, h = bx - bt * HH;
    const int r0 = wid * 16 + (lane >> 2);
    const int cl = 2 * (lane & 3);
    #pragma unroll
    for (int nd = 0; nd < 8; nd++) {
        int col = h * HD + nd * 8 + cl;
        if (r0 < NP) {
            float v0 = o[nd][0] * inv0, v1 = o[nd][1] * inv0;
            __nv_bfloat16 a0 = __float2bfloat16(v0), a1 = __float2bfloat16(v1);
            size_t ro = ((size_t)bt * NP + r0) * AKW + col;
            *(uint32_t*)(g_Ac + ro)      = pk2(a0, a1);
            *(uint32_t*)(g_Ac + ro + CC) = pk2(__float2bfloat16(v0 - __bfloat162float(a0)),
                                               __float2bfloat16(v1 - __bfloat162float(a1)));
        }
        if (r0 + 8 < NP) {
            float v2 = o[nd][2] * inv1, v3 = o[nd][3] * inv1;
            __nv_bfloat16 a2 = __float2bfloat16(v2), a3 = __float2bfloat16(v3);
            size_t ro = ((size_t)bt * NP + r0 + 8) * AKW + col;
            *(uint32_t*)(g_Ac + ro)      = pk2(a2, a3);
            *(uint32_t*)(g_Ac + ro + CC) = pk2(__float2bfloat16(v2 - __bfloat162float(a2)),
                                               __float2bfloat16(v3 - __bfloat162float(a3)));
        }
    }
}

/* ---------------- launch --------------------------------------------------- */
extern "C" void kernel_launch(void* const* d_in, const int* in_sizes, int n_in,
                              void* d_out, int out_size) {
    const float* x     = (const float*)d_in[0];
    const float* Wqkv  = (const float*)d_in[1];
    const float* bqkv  = (const float*)d_in[2];
    const float* Wproj = (const float*)d_in[3];
    const float* bproj = (const float*)d_in[4];
    float* out = (float*)d_out;

    cudaFuncSetAttribute(attn_mma, cudaFuncAttributeMaxDynamicSharedMemorySize, ATT_SMEM);
    cudaFuncSetAttribute(qkv_mma,  cudaFuncAttributeMaxDynamicSharedMemorySize, SMEM_SZ);
    cudaFuncSetAttribute(proj_mma, cudaFuncAttributeMaxDynamicSharedMemorySize, SMEM_SZ);

    conv_A <<<(MROWS * 96 + 255) / 256, 256>>>(x);
    conv_Wq<<<(C3 * 96 + 255) / 256, 256>>>(Wqkv);
    conv_Wp<<<CC, CC>>>(Wproj);
    qkv_mma<<<dim3(C3 / 128, MROWS / 128), 256, SMEM_SZ>>>(bqkv);
    attn_mma<<<NBH, 416, ATT_SMEM>>>();
    proj_mma<<<dim3(CC / 128, MROWS / 128), 256, SMEM_SZ>>>(bproj, out);
}

// round 9
// speedup vs baseline: 3.6009x; 1.3980x over previous
#include <cuda_runtime.h>
#include <cuda_fp16.h>
#include <math_constants.h>
#include <cstdint>

#define BB 8
#define TT 64
#define NP 196
#define HH 6
#define HD 64
#define CC 384
#define C3 1152
#define AKW 768              /* A stored [hi|lo] fp16 */
#define BKW 384              /* W stored hi-only fp16 */
#define BT (BB*TT)           /* 512 */
#define MROWS (BT*NP)        /* 100352 */
#define NBH (BT*HH)          /* 3072 */
#define QK_SCALE 0.125f

#define BK 64
#define NKT 12               /* logical K' = 768 */
#define STRB 144             /* smem row stride: 64 fp16 + 8 pad */
#define STAGE_BYTES (128*STRB)          /* 18432 */
#define B_REGION (3*STAGE_BYTES)
#define SMEM_SZ (6*STAGE_BYTES)         /* 110592; epilogue (67584) reuses */

/* attention smem: K hi + V hi, 208-row regions (pad rows masked/zeroed) */
#define KSTRB 144
#define SM_KH 0
#define SM_VH 29952          /* 208*144 */
#define ATT_SMEM 59904

/* ---------------- scratch ------------------------------------------------- */
__device__ __half g_Qh[(size_t)NBH*NP*HD];     /* [bh][n][d] hi, pre-scaled */
__device__ __half g_Ql[(size_t)NBH*NP*HD];
__device__ __half g_Kh[(size_t)NBH*NP*HD];
__device__ __half g_Vh[(size_t)NBH*NP*HD];
__device__ __half g_Xc[(size_t)MROWS*AKW];     /* X [hi|lo] */
__device__ __half g_Ac[(size_t)MROWS*AKW];     /* attn out [hi|lo] */
__device__ __half g_Wqc[(size_t)C3*BKW];       /* Wqkv hi */
__device__ __half g_Wpc[(size_t)CC*BKW];       /* Wproj permuted hi */

/* ---------------- PTX helpers --------------------------------------------- */
__device__ __forceinline__ uint32_t smem_u32(const void* p) {
    uint32_t a;
    asm("{ .reg .u64 t; cvta.to.shared.u64 t, %1; cvt.u32.u64 %0, t; }" : "=r"(a) : "l"(p));
    return a;
}
__device__ __forceinline__ void cpasync16(uint32_t s, const void* g) {
    asm volatile("cp.async.cg.shared.global [%0], [%1], 16;" :: "r"(s), "l"(g));
}
#define CP_COMMIT() asm volatile("cp.async.commit_group;" ::: "memory")
#define CP_WAIT1()  asm volatile("cp.async.wait_group 1;" ::: "memory")
#define CP_WAIT0()  asm volatile("cp.async.wait_group 0;" ::: "memory")

__device__ __forceinline__ void ldsm_x4(uint32_t* r, uint32_t addr) {
    asm volatile("ldmatrix.sync.aligned.m8n8.x4.shared.b16 {%0,%1,%2,%3}, [%4];"
                 : "=r"(r[0]), "=r"(r[1]), "=r"(r[2]), "=r"(r[3]) : "r"(addr));
}
__device__ __forceinline__ void ldsm_x2(uint32_t* r, uint32_t addr) {
    asm volatile("ldmatrix.sync.aligned.m8n8.x2.shared.b16 {%0,%1}, [%2];"
                 : "=r"(r[0]), "=r"(r[1]) : "r"(addr));
}
__device__ __forceinline__ void ldsm_x2_t(uint32_t* r, uint32_t addr) {
    asm volatile("ldmatrix.sync.aligned.m8n8.x2.trans.shared.b16 {%0,%1}, [%2];"
                 : "=r"(r[0]), "=r"(r[1]) : "r"(addr));
}
__device__ __forceinline__ void mma16816(float* c, const uint32_t* a, const uint32_t* b) {
    asm volatile("mma.sync.aligned.m16n8k16.row.col.f32.f16.f16.f32 "
                 "{%0,%1,%2,%3}, {%4,%5,%6,%7}, {%8,%9}, {%0,%1,%2,%3};"
                 : "+f"(c[0]), "+f"(c[1]), "+f"(c[2]), "+f"(c[3])
                 : "r"(a[0]), "r"(a[1]), "r"(a[2]), "r"(a[3]), "r"(b[0]), "r"(b[1]));
}
__device__ __forceinline__ uint32_t pk2h(__half a, __half b) {
    __half2 t; t.x = a; t.y = b;
    return *(uint32_t*)&t;
}

/* ---------------- split conversions (fp16 hi/lo) --------------------------- */
__global__ __launch_bounds__(256) void conv_A(const float* __restrict__ src) {
    int t = blockIdx.x * 256 + threadIdx.x;
    if (t >= MROWS * 96) return;
    int m = t / 96, q = t - m * 96;
    float4 v = *(const float4*)(src + (size_t)m * CC + q * 4);
    __half h0 = __float2half_rn(v.x), h1 = __float2half_rn(v.y);
    __half h2 = __float2half_rn(v.z), h3 = __float2half_rn(v.w);
    uint2 uh; uh.x = pk2h(h0, h1); uh.y = pk2h(h2, h3);
    uint2 ul;
    ul.x = pk2h(__float2half_rn(v.x - __half2float(h0)),
                __float2half_rn(v.y - __half2float(h1)));
    ul.y = pk2h(__float2half_rn(v.z - __half2float(h2)),
                __float2half_rn(v.w - __half2float(h3)));
    __half* d = g_Xc + (size_t)m * AKW + q * 4;
    *(uint2*)d = uh;
    *(uint2*)(d + CC) = ul;
}
__global__ __launch_bounds__(256) void conv_Wq(const float* __restrict__ src) {
    int t = blockIdx.x * 256 + threadIdx.x;
    if (t >= C3 * 96) return;
    int o = t / 96, q = t - o * 96;
    float4 v = *(const float4*)(src + (size_t)o * CC + q * 4);
    uint2 uh;
    uh.x = pk2h(__float2half_rn(v.x), __float2half_rn(v.y));
    uh.y = pk2h(__float2half_rn(v.z), __float2half_rn(v.w));
    *(uint2*)(g_Wqc + (size_t)o * BKW + q * 4) = uh;
}
__global__ void conv_Wp(const float* __restrict__ src) {
    int o = blockIdx.x, c = threadIdx.x;
    int h = c >> 6, d = c & 63;
    g_Wpc[(size_t)o * BKW + c] = __float2half_rn(src[(size_t)o * CC + d * HH + h]);
}

/* ---------------- mma.sync GEMM mainloop (fp16x2, BK=64, 3-stage) ---------- */
/* A [hi|lo] 768 wide: ak = kt*64. W hi-only 384 wide: bk = (kt%6)*64.        */
__device__ __forceinline__ void prefetch_kt(const __half* Ab, const __half* Bb,
                                            uint32_t sm, int kt, int tid) {
    const int st = kt % 3;
    const int ak = kt * 64, bk = (kt % 6) * 64;
    const uint32_t sa = sm + st * STAGE_BYTES;
    const uint32_t sb = sm + B_REGION + st * STAGE_BYTES;
    #pragma unroll
    for (int it = 0; it < 4; it++) {
        int idx = it * 256 + tid;
        int r = idx >> 3, jj = idx & 7;
        cpasync16(sa + r * STRB + jj * 16, Ab + (size_t)r * AKW + ak + jj * 8);
        cpasync16(sb + r * STRB + jj * 16, Bb + (size_t)r * BKW + bk + jj * 8);
    }
}
__device__ __forceinline__ void gemm_mainloop(const __half* __restrict__ A,
                                              const __half* __restrict__ Bm,
                                              int rowBase, int colBase,
                                              uint32_t sm, float acc[4][4][4]) {
    const int tid  = threadIdx.x;
    const int wid  = tid >> 5, lane = tid & 31;
    const int wr   = wid >> 2, wc = wid & 3;

    #pragma unroll
    for (int i = 0; i < 4; i++)
        #pragma unroll
        for (int j = 0; j < 4; j++)
            #pragma unroll
            for (int k = 0; k < 4; k++) acc[i][j][k] = 0.f;

    const __half* Ab = A + (size_t)rowBase * AKW;
    const __half* Bb = Bm + (size_t)colBase * BKW;

    prefetch_kt(Ab, Bb, sm, 0, tid); CP_COMMIT();
    prefetch_kt(Ab, Bb, sm, 1, tid); CP_COMMIT();

    const uint32_t aoff = (uint32_t)((wr * 64 + (lane & 15)) * STRB + ((lane >> 4) & 1) * 16);
    const uint32_t boff = (uint32_t)((wc * 32 + (lane & 7) + ((lane >> 4) & 1) * 8) * STRB
                                     + ((lane >> 3) & 1) * 16);

    #pragma unroll 1
    for (int kt = 0; kt < NKT; kt++) {
        CP_WAIT1();
        __syncthreads();
        if (kt + 2 < NKT) prefetch_kt(Ab, Bb, sm, kt + 2, tid);
        CP_COMMIT();

        const int st = kt % 3;
        const uint32_t aBase = sm + st * STAGE_BYTES + aoff;
        const uint32_t bBase = sm + B_REGION + st * STAGE_BYTES + boff;
        #pragma unroll
        for (int ks = 0; ks < 4; ks++) {
            uint32_t af[4][4], bf[2][4];
            #pragma unroll
            for (int i = 0; i < 4; i++)
                ldsm_x4(af[i], aBase + (uint32_t)(i * 16 * STRB + ks * 32));
            #pragma unroll
            for (int jj = 0; jj < 2; jj++)
                ldsm_x4(bf[jj], bBase + (uint32_t)(jj * 16 * STRB + ks * 32));
            #pragma unroll
            for (int i = 0; i < 4; i++) {
                mma16816(acc[i][0], af[i], bf[0]);
                mma16816(acc[i][1], af[i], bf[0] + 2);
                mma16816(acc[i][2], af[i], bf[1]);
                mma16816(acc[i][3], af[i], bf[1] + 2);
            }
        }
    }
    CP_WAIT0();
    __syncthreads();
}

__device__ __forceinline__ void acc_to_smem(float* eps, float acc[4][4][4]) {
    const int tid = threadIdx.x, wid = tid >> 5, lane = tid & 31;
    const int wr = wid >> 2, wc = wid & 3;
    const int rl = lane >> 2, cl = 2 * (lane & 3);
    #pragma unroll
    for (int i = 0; i < 4; i++) {
        #pragma unroll
        for (int j = 0; j < 4; j++) {
            int r = wr * 64 + i * 16 + rl;
            int c = wc * 32 + j * 8 + cl;
            eps[r * 132 + c]       = acc[i][j][0];
            eps[r * 132 + c + 1]   = acc[i][j][1];
            eps[(r + 8) * 132 + c] = acc[i][j][2];
            eps[(r + 8) * 132 + c + 1] = acc[i][j][3];
        }
    }
    __syncthreads();
}

/* ---------------- QKV GEMM kernel ------------------------------------------ */
__global__ __launch_bounds__(256) void qkv_mma(const float* __restrict__ bias) {
    extern __shared__ char dynsm[];
    uint32_t sm = smem_u32(dynsm);
    const int colBase = blockIdx.x * 128;
    const int rowBase = blockIdx.y * 128;

    float acc[4][4][4];
    gemm_mainloop(g_Xc, g_Wqc, rowBase, colBase, sm, acc);
    float* eps = (float*)dynsm;
    acc_to_smem(eps, acc);

    const int tid = threadIdx.x, w = tid >> 5, lane = tid & 31;
    const int s  = colBase / CC;
    const int hb = (colBase - s * CC) >> 6;
    const float mul = (s == 0) ? QK_SCALE : 1.0f;
    #pragma unroll
    for (int it = 0; it < 16; it++) {
        int run = (it * 8 + w) * 2 + (lane >> 4);
        int row = run >> 1, hh = run & 1, j = lane & 15;
        int m = rowBase + row;
        int bt = m / NP, n = m - bt * NP;
        float4 v = *(float4*)(eps + row * 132 + hh * 64 + j * 4);
        float4 bv = *(const float4*)(bias + colBase + hh * 64 + j * 4);
        v.x = (v.x + bv.x) * mul; v.y = (v.y + bv.y) * mul;
        v.z = (v.z + bv.z) * mul; v.w = (v.w + bv.w) * mul;
        __half h0 = __float2half_rn(v.x), h1 = __float2half_rn(v.y);
        __half h2 = __float2half_rn(v.z), h3 = __float2half_rn(v.w);
        uint2 uh; uh.x = pk2h(h0, h1); uh.y = pk2h(h2, h3);
        size_t off = ((size_t)(bt * HH + hb + hh) * NP + n) * HD + j * 4;
        if (s == 0) {
            uint2 ul;
            ul.x = pk2h(__float2half_rn(v.x - __half2float(h0)),
                        __float2half_rn(v.y - __half2float(h1)));
            ul.y = pk2h(__float2half_rn(v.z - __half2float(h2)),
                        __float2half_rn(v.w - __half2float(h3)));
            *(uint2*)(g_Qh + off) = uh;
            *(uint2*)(g_Ql + off) = ul;
        } else if (s == 1) {
            *(uint2*)(g_Kh + off) = uh;
        } else {
            *(uint2*)(g_Vh + off) = uh;
        }
    }
}

/* ---------------- proj GEMM kernel ----------------------------------------- */
__global__ __launch_bounds__(256) void proj_mma(const float* __restrict__ bias,
                                                float* __restrict__ out) {
    extern __shared__ char dynsm[];
    uint32_t sm = smem_u32(dynsm);
    const int colBase = blockIdx.x * 128;
    const int rowBase = blockIdx.y * 128;

    float acc[4][4][4];
    gemm_mainloop(g_Ac, g_Wpc, rowBase, colBase, sm, acc);
    float* eps = (float*)dynsm;
    acc_to_smem(eps, acc);

    const int tid = threadIdx.x, w = tid >> 5, lane = tid & 31;
    float4 bv = *(const float4*)(bias + colBase + lane * 4);
    #pragma unroll
    for (int it = 0; it < 16; it++) {
        int row = it * 8 + w;
        int m = rowBase + row;
        float4 v = *(float4*)(eps + row * 132 + lane * 4);
        v.x += bv.x; v.y += bv.y; v.z += bv.z; v.w += bv.w;
        *(float4*)(out + (size_t)m * CC + colBase + lane * 4) = v;
    }
}

/* ---------------- attention via mma.sync (fp16x2) -------------------------- */
template<int NT>
__device__ __forceinline__ void attn_chunk(uint32_t sb, int lane, int cbase,
                                           const uint32_t qh[4][4], const uint32_t ql[4][4],
                                           float o[8][4], float& lp0, float& lp1) {
    float s[NT][4];
    #pragma unroll
    for (int t = 0; t < NT; t++)
        #pragma unroll
        for (int e = 0; e < 4; e++) s[t][e] = 0.f;

    /* --- QK: (qh+ql)·kh --- */
    #pragma unroll
    for (int t = 0; t < NT; t++) {
        #pragma unroll
        for (int ks = 0; ks < 4; ks++) {
            uint32_t bh[2];
            uint32_t off = (uint32_t)((cbase + t * 8 + (lane & 7)) * KSTRB
                                      + ks * 32 + ((lane >> 3) & 1) * 16);
            ldsm_x2(bh, sb + SM_KH + off);
            mma16816(s[t], qh[ks], bh);
            mma16816(s[t], ql[ks], bh);
        }
    }

    /* --- exp + mask + pack P (fp16 hi/lo) --- */
    uint32_t phi[NT/2][4], plo[NT/2][4];
    #pragma unroll
    for (int t = 0; t < NT; t++) {
        int c0 = cbase + t * 8 + 2 * (lane & 3);
        float p0 = (c0     < NP) ? __expf(s[t][0]) : 0.f;
        float p1 = (c0 + 1 < NP) ? __expf(s[t][1]) : 0.f;
        float p2 = (c0     < NP) ? __expf(s[t][2]) : 0.f;
        float p3 = (c0 + 1 < NP) ? __expf(s[t][3]) : 0.f;
        lp0 += p0 + p1;
        lp1 += p2 + p3;
        __half h0 = __float2half_rn(p0), h1 = __float2half_rn(p1);
        __half h2 = __float2half_rn(p2), h3 = __float2half_rn(p3);
        int j = t >> 1, oreg = (t & 1) * 2;
        phi[j][oreg]     = pk2h(h0, h1);
        phi[j][oreg + 1] = pk2h(h2, h3);
        plo[j][oreg]     = pk2h(__float2half_rn(p0 - __half2float(h0)),
                                __float2half_rn(p1 - __half2float(h1)));
        plo[j][oreg + 1] = pk2h(__float2half_rn(p2 - __half2float(h2)),
                                __float2half_rn(p3 - __half2float(h3)));
    }

    /* --- PV: (phi+plo)·vh via ldmatrix.trans --- */
    #pragma unroll
    for (int j = 0; j < NT / 2; j++) {
        #pragma unroll
        for (int nd = 0; nd < 8; nd++) {
            uint32_t bh[2];
            uint32_t off = (uint32_t)((cbase + j * 16 + (lane & 15)) * KSTRB + nd * 16);
            ldsm_x2_t(bh, sb + SM_VH + off);
            mma16816(o[nd], phi[j], bh);
            mma16816(o[nd], plo[j], bh);
        }
    }
}

__global__ __launch_bounds__(416, 1) void attn_mma() {
    extern __shared__ char smc[];
    uint32_t sb = smem_u32(smc);
    const int bx = blockIdx.x;                 /* bt*6 + h */
    const int tid = threadIdx.x, wid = tid >> 5, lane = tid & 31;

    const size_t base = (size_t)bx * NP * HD;
    for (int i = tid; i < NP * 8; i += 416) {
        int r = i >> 3, j = i & 7;
        uint32_t doff = (uint32_t)(r * KSTRB + j * 16);
        *(uint4*)(smc + SM_KH + doff) = ((const uint4*)(g_Kh + base))[i];
        *(uint4*)(smc + SM_VH + doff) = ((const uint4*)(g_Vh + base))[i];
    }
    /* zero V pad rows 196-207 (NaN x 0 guard in PV) */
    if (tid < 108)
        *(uint4*)(smc + SM_VH + 196 * KSTRB + tid * 16) = make_uint4(0, 0, 0, 0);

    /* Q fragments straight from gmem (row-clamped) */
    uint32_t qh[4][4], ql[4][4];
    {
        const uint32_t* qhp = (const uint32_t*)(g_Qh + base);
        const uint32_t* qlp = (const uint32_t*)(g_Ql + base);
        int r  = wid * 16 + (lane >> 2);
        int r2 = r + 8;
        int ra  = (r  < NP) ? r  : NP - 1;
        int r2a = (r2 < NP) ? r2 : NP - 1;
        int c = lane & 3;
        #pragma unroll
        for (int ks = 0; ks < 4; ks++) {
            qh[ks][0] = qhp[ra  * 32 + ks * 8 + c];
            qh[ks][1] = qhp[r2a * 32 + ks * 8 + c];
            qh[ks][2] = qhp[ra  * 32 + ks * 8 + 4 + c];
            qh[ks][3] = qhp[r2a * 32 + ks * 8 + 4 + c];
            ql[ks][0] = qlp[ra  * 32 + ks * 8 + c];
            ql[ks][1] = qlp[r2a * 32 + ks * 8 + c];
            ql[ks][2] = qlp[ra  * 32 + ks * 8 + 4 + c];
            ql[ks][3] = qlp[r2a * 32 + ks * 8 + 4 + c];
        }
    }
    __syncthreads();

    float o[8][4];
    #pragma unroll
    for (int nd = 0; nd < 8; nd++)
        #pragma unroll
        for (int e = 0; e < 4; e++) o[nd][e] = 0.f;
    float lp0 = 0.f, lp1 = 0.f;

    attn_chunk<14>(sb, lane, 0,   qh, ql, o, lp0, lp1);
    attn_chunk<12>(sb, lane, 112, qh, ql, o, lp0, lp1);

    lp0 += __shfl_xor_sync(0xFFFFFFFFu, lp0, 1);
    lp0 += __shfl_xor_sync(0xFFFFFFFFu, lp0, 2);
    lp1 += __shfl_xor_sync(0xFFFFFFFFu, lp1, 1);
    lp1 += __shfl_xor_sync(0xFFFFFFFFu, lp1, 2);
    const float inv0 = 1.0f / lp0, inv1 = 1.0f / lp1;

    const int bt = bx / HH, h = bx - bt * HH;
    const int r0 = wid * 16 + (lane >> 2);
    const int cl = 2 * (lane & 3);
    #pragma unroll
    for (int nd = 0; nd < 8; nd++) {
        int col = h * HD + nd * 8 + cl;
        if (r0 < NP) {
            float v0 = o[nd][0] * inv0, v1 = o[nd][1] * inv0;
            __half a0 = __float2half_rn(v0), a1 = __float2half_rn(v1);
            size_t ro = ((size_t)bt * NP + r0) * AKW + col;
            *(uint32_t*)(g_Ac + ro)      = pk2h(a0, a1);
            *(uint32_t*)(g_Ac + ro + CC) = pk2h(__float2half_rn(v0 - __half2float(a0)),
                                                __float2half_rn(v1 - __half2float(a1)));
        }
        if (r0 + 8 < NP) {
            float v2 = o[nd][2] * inv1, v3 = o[nd][3] * inv1;
            __half a2 = __float2half_rn(v2), a3 = __float2half_rn(v3);
            size_t ro = ((size_t)bt * NP + r0 + 8) * AKW + col;
            *(uint32_t*)(g_Ac + ro)      = pk2h(a2, a3);
            *(uint32_t*)(g_Ac + ro + CC) = pk2h(__float2half_rn(v2 - __half2float(a2)),
                                                __float2half_rn(v3 - __half2float(a3)));
        }
    }
}

/* ---------------- launch --------------------------------------------------- */
extern "C" void kernel_launch(void* const* d_in, const int* in_sizes, int n_in,
                              void* d_out, int out_size) {
    const float* x     = (const float*)d_in[0];
    const float* Wqkv  = (const float*)d_in[1];
    const float* bqkv  = (const float*)d_in[2];
    const float* Wproj = (const float*)d_in[3];
    const float* bproj = (const float*)d_in[4];
    float* out = (float*)d_out;

    cudaFuncSetAttribute(attn_mma, cudaFuncAttributeMaxDynamicSharedMemorySize, ATT_SMEM);
    cudaFuncSetAttribute(qkv_mma,  cudaFuncAttributeMaxDynamicSharedMemorySize, SMEM_SZ);
    cudaFuncSetAttribute(proj_mma, cudaFuncAttributeMaxDynamicSharedMemorySize, SMEM_SZ);

    conv_A <<<(MROWS * 96 + 255) / 256, 256>>>(x);
    conv_Wq<<<(C3 * 96 + 255) / 256, 256>>>(Wqkv);
    conv_Wp<<<CC, CC>>>(Wproj);
    qkv_mma<<<dim3(C3 / 128, MROWS / 128), 256, SMEM_SZ>>>(bqkv);
    attn_mma<<<NBH, 416, ATT_SMEM>>>();
    proj_mma<<<dim3(CC / 128, MROWS / 128), 256, SMEM_SZ>>>(bproj, out);
}

// round 10
// speedup vs baseline: 4.2422x; 1.1781x over previous
#include <cuda_runtime.h>
#include <cuda_fp16.h>
#include <math_constants.h>
#include <cstdint>

#define BB 8
#define TT 64
#define NP 196
#define HH 6
#define HD 64
#define CC 384
#define C3 1152
#define AKW 768              /* A stored [hi|lo] fp16 */
#define BKW 384              /* W stored hi-only fp16 */
#define BT (BB*TT)           /* 512 */
#define MROWS (BT*NP)        /* 100352 */
#define NBH (BT*HH)          /* 3072 */
#define QK_SCALE 0.125f

#define BK 64
#define STRB 144             /* smem row stride: 64 fp16 + 8 pad */
#define STAGE_BYTES (128*STRB)          /* 18432 */
#define B_REGION (3*STAGE_BYTES)
#define SMEM_SZ (6*STAGE_BYTES)         /* 110592; epilogue (67584) reuses */

/* attention smem: K hi + V hi, 208-row regions (pad rows masked/zeroed) */
#define KSTRB 144
#define SM_KH 0
#define SM_VH 29952          /* 208*144 */
#define ATT_SMEM 59904

/* ---------------- scratch ------------------------------------------------- */
__device__ __half g_Qh[(size_t)NBH*NP*HD];     /* [bh][n][d] hi, pre-scaled */
__device__ __half g_Ql[(size_t)NBH*NP*HD];
__device__ __half g_Kh[(size_t)NBH*NP*HD];
__device__ __half g_Vh[(size_t)NBH*NP*HD];
__device__ __half g_Xc[(size_t)MROWS*AKW];     /* X [hi|lo] */
__device__ __half g_Ac[(size_t)MROWS*AKW];     /* attn out [hi|lo] */
__device__ __half g_Wqc[(size_t)C3*BKW];       /* Wqkv hi */
__device__ __half g_Wpc[(size_t)CC*BKW];       /* Wproj permuted hi */

/* ---------------- PTX helpers --------------------------------------------- */
__device__ __forceinline__ uint32_t smem_u32(const void* p) {
    uint32_t a;
    asm("{ .reg .u64 t; cvta.to.shared.u64 t, %1; cvt.u32.u64 %0, t; }" : "=r"(a) : "l"(p));
    return a;
}
__device__ __forceinline__ void cpasync16(uint32_t s, const void* g) {
    asm volatile("cp.async.cg.shared.global [%0], [%1], 16;" :: "r"(s), "l"(g));
}
#define CP_COMMIT() asm volatile("cp.async.commit_group;" ::: "memory")
#define CP_WAIT1()  asm volatile("cp.async.wait_group 1;" ::: "memory")
#define CP_WAIT0()  asm volatile("cp.async.wait_group 0;" ::: "memory")

__device__ __forceinline__ void ldsm_x4(uint32_t* r, uint32_t addr) {
    asm volatile("ldmatrix.sync.aligned.m8n8.x4.shared.b16 {%0,%1,%2,%3}, [%4];"
                 : "=r"(r[0]), "=r"(r[1]), "=r"(r[2]), "=r"(r[3]) : "r"(addr));
}
__device__ __forceinline__ void ldsm_x2(uint32_t* r, uint32_t addr) {
    asm volatile("ldmatrix.sync.aligned.m8n8.x2.shared.b16 {%0,%1}, [%2];"
                 : "=r"(r[0]), "=r"(r[1]) : "r"(addr));
}
__device__ __forceinline__ void ldsm_x2_t(uint32_t* r, uint32_t addr) {
    asm volatile("ldmatrix.sync.aligned.m8n8.x2.trans.shared.b16 {%0,%1}, [%2];"
                 : "=r"(r[0]), "=r"(r[1]) : "r"(addr));
}
__device__ __forceinline__ void mma16816(float* c, const uint32_t* a, const uint32_t* b) {
    asm volatile("mma.sync.aligned.m16n8k16.row.col.f32.f16.f16.f32 "
                 "{%0,%1,%2,%3}, {%4,%5,%6,%7}, {%8,%9}, {%0,%1,%2,%3};"
                 : "+f"(c[0]), "+f"(c[1]), "+f"(c[2]), "+f"(c[3])
                 : "r"(a[0]), "r"(a[1]), "r"(a[2]), "r"(a[3]), "r"(b[0]), "r"(b[1]));
}
__device__ __forceinline__ uint32_t pk2h(__half a, __half b) {
    __half2 t; t.x = a; t.y = b;
    return *(uint32_t*)&t;
}

/* ---------------- split conversions (fp16 hi/lo) --------------------------- */
__global__ __launch_bounds__(256) void conv_A(const float* __restrict__ src) {
    int t = blockIdx.x * 256 + threadIdx.x;
    if (t >= MROWS * 96) return;
    int m = t / 96, q = t - m * 96;
    float4 v = *(const float4*)(src + (size_t)m * CC + q * 4);
    __half h0 = __float2half_rn(v.x), h1 = __float2half_rn(v.y);
    __half h2 = __float2half_rn(v.z), h3 = __float2half_rn(v.w);
    uint2 uh; uh.x = pk2h(h0, h1); uh.y = pk2h(h2, h3);
    uint2 ul;
    ul.x = pk2h(__float2half_rn(v.x - __half2float(h0)),
                __float2half_rn(v.y - __half2float(h1)));
    ul.y = pk2h(__float2half_rn(v.z - __half2float(h2)),
                __float2half_rn(v.w - __half2float(h3)));
    __half* d = g_Xc + (size_t)m * AKW + q * 4;
    *(uint2*)d = uh;
    *(uint2*)(d + CC) = ul;
}
__global__ __launch_bounds__(256) void conv_Wq(const float* __restrict__ src) {
    int t = blockIdx.x * 256 + threadIdx.x;
    if (t >= C3 * 96) return;
    int o = t / 96, q = t - o * 96;
    float4 v = *(const float4*)(src + (size_t)o * CC + q * 4);
    uint2 uh;
    uh.x = pk2h(__float2half_rn(v.x), __float2half_rn(v.y));
    uh.y = pk2h(__float2half_rn(v.z), __float2half_rn(v.w));
    *(uint2*)(g_Wqc + (size_t)o * BKW + q * 4) = uh;
}
__global__ void conv_Wp(const float* __restrict__ src) {
    int o = blockIdx.x, c = threadIdx.x;
    int h = c >> 6, d = c & 63;
    g_Wpc[(size_t)o * BKW + c] = __float2half_rn(src[(size_t)o * CC + d * HH + h]);
}

/* ---------------- mma.sync GEMM mainloop (fp16, BK=64, 3-stage) ------------ */
/* A [hi|lo] 768 wide: ak = kt*64 (walks hi then lo). W hi 384: bk=(kt%6)*64. */
/* nkt=12 -> (A.hi + A.lo)*W ; nkt=6 -> A.hi*W only.                          */
__device__ __forceinline__ void prefetch_kt(const __half* Ab, const __half* Bb,
                                            uint32_t sm, int kt, int tid) {
    const int st = kt % 3;
    const int ak = kt * 64, bk = (kt % 6) * 64;
    const uint32_t sa = sm + st * STAGE_BYTES;
    const uint32_t sb = sm + B_REGION + st * STAGE_BYTES;
    #pragma unroll
    for (int it = 0; it < 4; it++) {
        int idx = it * 256 + tid;
        int r = idx >> 3, jj = idx & 7;
        cpasync16(sa + r * STRB + jj * 16, Ab + (size_t)r * AKW + ak + jj * 8);
        cpasync16(sb + r * STRB + jj * 16, Bb + (size_t)r * BKW + bk + jj * 8);
    }
}
__device__ __forceinline__ void gemm_mainloop(const __half* __restrict__ A,
                                              const __half* __restrict__ Bm,
                                              int rowBase, int colBase, int nkt,
                                              uint32_t sm, float acc[4][4][4]) {
    const int tid  = threadIdx.x;
    const int wid  = tid >> 5, lane = tid & 31;
    const int wr   = wid >> 2, wc = wid & 3;

    #pragma unroll
    for (int i = 0; i < 4; i++)
        #pragma unroll
        for (int j = 0; j < 4; j++)
            #pragma unroll
            for (int k = 0; k < 4; k++) acc[i][j][k] = 0.f;

    const __half* Ab = A + (size_t)rowBase * AKW;
    const __half* Bb = Bm + (size_t)colBase * BKW;

    prefetch_kt(Ab, Bb, sm, 0, tid); CP_COMMIT();
    prefetch_kt(Ab, Bb, sm, 1, tid); CP_COMMIT();

    const uint32_t aoff = (uint32_t)((wr * 64 + (lane & 15)) * STRB + ((lane >> 4) & 1) * 16);
    const uint32_t boff = (uint32_t)((wc * 32 + (lane & 7) + ((lane >> 4) & 1) * 8) * STRB
                                     + ((lane >> 3) & 1) * 16);

    #pragma unroll 1
    for (int kt = 0; kt < nkt; kt++) {
        CP_WAIT1();
        __syncthreads();
        if (kt + 2 < nkt) prefetch_kt(Ab, Bb, sm, kt + 2, tid);
        CP_COMMIT();

        const int st = kt % 3;
        const uint32_t aBase = sm + st * STAGE_BYTES + aoff;
        const uint32_t bBase = sm + B_REGION + st * STAGE_BYTES + boff;
        #pragma unroll
        for (int ks = 0; ks < 4; ks++) {
            uint32_t af[4][4], bf[2][4];
            #pragma unroll
            for (int i = 0; i < 4; i++)
                ldsm_x4(af[i], aBase + (uint32_t)(i * 16 * STRB + ks * 32));
            #pragma unroll
            for (int jj = 0; jj < 2; jj++)
                ldsm_x4(bf[jj], bBase + (uint32_t)(jj * 16 * STRB + ks * 32));
            #pragma unroll
            for (int i = 0; i < 4; i++) {
                mma16816(acc[i][0], af[i], bf[0]);
                mma16816(acc[i][1], af[i], bf[0] + 2);
                mma16816(acc[i][2], af[i], bf[1]);
                mma16816(acc[i][3], af[i], bf[1] + 2);
            }
        }
    }
    CP_WAIT0();
    __syncthreads();
}

__device__ __forceinline__ void acc_to_smem(float* eps, float acc[4][4][4]) {
    const int tid = threadIdx.x, wid = tid >> 5, lane = tid & 31;
    const int wr = wid >> 2, wc = wid & 3;
    const int rl = lane >> 2, cl = 2 * (lane & 3);
    #pragma unroll
    for (int i = 0; i < 4; i++) {
        #pragma unroll
        for (int j = 0; j < 4; j++) {
            int r = wr * 64 + i * 16 + rl;
            int c = wc * 32 + j * 8 + cl;
            eps[r * 132 + c]       = acc[i][j][0];
            eps[r * 132 + c + 1]   = acc[i][j][1];
            eps[(r + 8) * 132 + c] = acc[i][j][2];
            eps[(r + 8) * 132 + c + 1] = acc[i][j][3];
        }
    }
    __syncthreads();
}

/* ---------------- QKV GEMM kernel ------------------------------------------ */
/* Q cols (s=0): 2-pass (nkt=12).  K/V cols: 1-pass hi-only (nkt=6).          */
__global__ __launch_bounds__(256) void qkv_mma(const float* __restrict__ bias) {
    extern __shared__ char dynsm[];
    uint32_t sm = smem_u32(dynsm);
    const int colBase = blockIdx.x * 128;
    const int rowBase = blockIdx.y * 128;
    const int s  = colBase / CC;
    const int nkt = (s == 0) ? 12 : 6;

    float acc[4][4][4];
    gemm_mainloop(g_Xc, g_Wqc, rowBase, colBase, nkt, sm, acc);
    float* eps = (float*)dynsm;
    acc_to_smem(eps, acc);

    const int tid = threadIdx.x, w = tid >> 5, lane = tid & 31;
    const int hb = (colBase - s * CC) >> 6;
    const float mul = (s == 0) ? QK_SCALE : 1.0f;
    #pragma unroll
    for (int it = 0; it < 16; it++) {
        int run = (it * 8 + w) * 2 + (lane >> 4);
        int row = run >> 1, hh = run & 1, j = lane & 15;
        int m = rowBase + row;
        int bt = m / NP, n = m - bt * NP;
        float4 v = *(float4*)(eps + row * 132 + hh * 64 + j * 4);
        float4 bv = *(const float4*)(bias + colBase + hh * 64 + j * 4);
        v.x = (v.x + bv.x) * mul; v.y = (v.y + bv.y) * mul;
        v.z = (v.z + bv.z) * mul; v.w = (v.w + bv.w) * mul;
        __half h0 = __float2half_rn(v.x), h1 = __float2half_rn(v.y);
        __half h2 = __float2half_rn(v.z), h3 = __float2half_rn(v.w);
        uint2 uh; uh.x = pk2h(h0, h1); uh.y = pk2h(h2, h3);
        size_t off = ((size_t)(bt * HH + hb + hh) * NP + n) * HD + j * 4;
        if (s == 0) {
            uint2 ul;
            ul.x = pk2h(__float2half_rn(v.x - __half2float(h0)),
                        __float2half_rn(v.y - __half2float(h1)));
            ul.y = pk2h(__float2half_rn(v.z - __half2float(h2)),
                        __float2half_rn(v.w - __half2float(h3)));
            *(uint2*)(g_Qh + off) = uh;
            *(uint2*)(g_Ql + off) = ul;
        } else if (s == 1) {
            *(uint2*)(g_Kh + off) = uh;
        } else {
            *(uint2*)(g_Vh + off) = uh;
        }
    }
}

/* ---------------- proj GEMM kernel ----------------------------------------- */
__global__ __launch_bounds__(256) void proj_mma(const float* __restrict__ bias,
                                                float* __restrict__ out) {
    extern __shared__ char dynsm[];
    uint32_t sm = smem_u32(dynsm);
    const int colBase = blockIdx.x * 128;
    const int rowBase = blockIdx.y * 128;

    float acc[4][4][4];
    gemm_mainloop(g_Ac, g_Wpc, rowBase, colBase, 12, sm, acc);
    float* eps = (float*)dynsm;
    acc_to_smem(eps, acc);

    const int tid = threadIdx.x, w = tid >> 5, lane = tid & 31;
    float4 bv = *(const float4*)(bias + colBase + lane * 4);
    #pragma unroll
    for (int it = 0; it < 16; it++) {
        int row = it * 8 + w;
        int m = rowBase + row;
        float4 v = *(float4*)(eps + row * 132 + lane * 4);
        v.x += bv.x; v.y += bv.y; v.z += bv.z; v.w += bv.w;
        *(float4*)(out + (size_t)m * CC + colBase + lane * 4) = v;
    }
}

/* ---------------- attention via mma.sync (fp16x2) -------------------------- */
template<int NT>
__device__ __forceinline__ void attn_chunk(uint32_t sb, int lane, int cbase,
                                           const uint32_t qh[4][4], const uint32_t ql[4][4],
                                           float o[8][4], float& lp0, float& lp1) {
    float s[NT][4];
    #pragma unroll
    for (int t = 0; t < NT; t++)
        #pragma unroll
        for (int e = 0; e < 4; e++) s[t][e] = 0.f;

    /* --- QK: (qh+ql)·kh --- */
    #pragma unroll
    for (int t = 0; t < NT; t++) {
        #pragma unroll
        for (int ks = 0; ks < 4; ks++) {
            uint32_t bh[2];
            uint32_t off = (uint32_t)((cbase + t * 8 + (lane & 7)) * KSTRB
                                      + ks * 32 + ((lane >> 3) & 1) * 16);
            ldsm_x2(bh, sb + SM_KH + off);
            mma16816(s[t], qh[ks], bh);
            mma16816(s[t], ql[ks], bh);
        }
    }

    /* --- exp + mask + pack P (fp16 hi/lo) --- */
    uint32_t phi[NT/2][4], plo[NT/2][4];
    #pragma unroll
    for (int t = 0; t < NT; t++) {
        int c0 = cbase + t * 8 + 2 * (lane & 3);
        float p0 = (c0     < NP) ? __expf(s[t][0]) : 0.f;
        float p1 = (c0 + 1 < NP) ? __expf(s[t][1]) : 0.f;
        float p2 = (c0     < NP) ? __expf(s[t][2]) : 0.f;
        float p3 = (c0 + 1 < NP) ? __expf(s[t][3]) : 0.f;
        lp0 += p0 + p1;
        lp1 += p2 + p3;
        __half h0 = __float2half_rn(p0), h1 = __float2half_rn(p1);
        __half h2 = __float2half_rn(p2), h3 = __float2half_rn(p3);
        int j = t >> 1, oreg = (t & 1) * 2;
        phi[j][oreg]     = pk2h(h0, h1);
        phi[j][oreg + 1] = pk2h(h2, h3);
        plo[j][oreg]     = pk2h(__float2half_rn(p0 - __half2float(h0)),
                                __float2half_rn(p1 - __half2float(h1)));
        plo[j][oreg + 1] = pk2h(__float2half_rn(p2 - __half2float(h2)),
                                __float2half_rn(p3 - __half2float(h3)));
    }

    /* --- PV: (phi+plo)·vh via ldmatrix.trans --- */
    #pragma unroll
    for (int j = 0; j < NT / 2; j++) {
        #pragma unroll
        for (int nd = 0; nd < 8; nd++) {
            uint32_t bh[2];
            uint32_t off = (uint32_t)((cbase + j * 16 + (lane & 15)) * KSTRB + nd * 16);
            ldsm_x2_t(bh, sb + SM_VH + off);
            mma16816(o[nd], phi[j], bh);
            mma16816(o[nd], plo[j], bh);
        }
    }
}

__global__ __launch_bounds__(416, 1) void attn_mma() {
    extern __shared__ char smc[];
    uint32_t sb = smem_u32(smc);
    const int bx = blockIdx.x;                 /* bt*6 + h */
    const int tid = threadIdx.x, wid = tid >> 5, lane = tid & 31;

    const size_t base = (size_t)bx * NP * HD;
    for (int i = tid; i < NP * 8; i += 416) {
        int r = i >> 3, j = i & 7;
        uint32_t doff = (uint32_t)(r * KSTRB + j * 16);
        *(uint4*)(smc + SM_KH + doff) = ((const uint4*)(g_Kh + base))[i];
        *(uint4*)(smc + SM_VH + doff) = ((const uint4*)(g_Vh + base))[i];
    }
    /* zero V pad rows 196-207 (NaN x 0 guard in PV) */
    if (tid < 108)
        *(uint4*)(smc + SM_VH + 196 * KSTRB + tid * 16) = make_uint4(0, 0, 0, 0);

    /* Q fragments straight from gmem (row-clamped) */
    uint32_t qh[4][4], ql[4][4];
    {
        const uint32_t* qhp = (const uint32_t*)(g_Qh + base);
        const uint32_t* qlp = (const uint32_t*)(g_Ql + base);
        int r  = wid * 16 + (lane >> 2);
        int r2 = r + 8;
        int ra  = (r  < NP) ? r  : NP - 1;
        int r2a = (r2 < NP) ? r2 : NP - 1;
        int c = lane & 3;
        #pragma unroll
        for (int ks = 0; ks < 4; ks++) {
            qh[ks][0] = qhp[ra  * 32 + ks * 8 + c];
            qh[ks][1] = qhp[r2a * 32 + ks * 8 + c];
            qh[ks][2] = qhp[ra  * 32 + ks * 8 + 4 + c];
            qh[ks][3] = qhp[r2a * 32 + ks * 8 + 4 + c];
            ql[ks][0] = qlp[ra  * 32 + ks * 8 + c];
            ql[ks][1] = qlp[r2a * 32 + ks * 8 + c];
            ql[ks][2] = qlp[ra  * 32 + ks * 8 + 4 + c];
            ql[ks][3] = qlp[r2a * 32 + ks * 8 + 4 + c];
        }
    }
    __syncthreads();

    float o[8][4];
    #pragma unroll
    for (int nd = 0; nd < 8; nd++)
        #pragma unroll
        for (int e = 0; e < 4; e++) o[nd][e] = 0.f;
    float lp0 = 0.f, lp1 = 0.f;

    attn_chunk<14>(sb, lane, 0,   qh, ql, o, lp0, lp1);
    attn_chunk<12>(sb, lane, 112, qh, ql, o, lp0, lp1);

    lp0 += __shfl_xor_sync(0xFFFFFFFFu, lp0, 1);
    lp0 += __shfl_xor_sync(0xFFFFFFFFu, lp0, 2);
    lp1 += __shfl_xor_sync(0xFFFFFFFFu, lp1, 1);
    lp1 += __shfl_xor_sync(0xFFFFFFFFu, lp1, 2);
    const float inv0 = 1.0f / lp0, inv1 = 1.0f / lp1;

    const int bt = bx / HH, h = bx - bt * HH;
    const int r0 = wid * 16 + (lane >> 2);
    const int cl = 2 * (lane & 3);
    #pragma unroll
    for (int nd = 0; nd < 8; nd++) {
        int col = h * HD + nd * 8 + cl;
        if (r0 < NP) {
            float v0 = o[nd][0] * inv0, v1 = o[nd][1] * inv0;
            __half a0 = __float2half_rn(v0), a1 = __float2half_rn(v1);
            size_t ro = ((size_t)bt * NP + r0) * AKW + col;
            *(uint32_t*)(g_Ac + ro)      = pk2h(a0, a1);
            *(uint32_t*)(g_Ac + ro + CC) = pk2h(__float2half_rn(v0 - __half2float(a0)),
                                                __float2half_rn(v1 - __half2float(a1)));
        }
        if (r0 + 8 < NP) {
            float v2 = o[nd][2] * inv1, v3 = o[nd][3] * inv1;
            __half a2 = __float2half_rn(v2), a3 = __float2half_rn(v3);
            size_t ro = ((size_t)bt * NP + r0 + 8) * AKW + col;
            *(uint32_t*)(g_Ac + ro)      = pk2h(a2, a3);
            *(uint32_t*)(g_Ac + ro + CC) = pk2h(__float2half_rn(v2 - __half2float(a2)),
                                                __float2half_rn(v3 - __half2float(a3)));
        }
    }
}

/* ---------------- launch --------------------------------------------------- */
extern "C" void kernel_launch(void* const* d_in, const int* in_sizes, int n_in,
                              void* d_out, int out_size) {
    const float* x     = (const float*)d_in[0];
    const float* Wqkv  = (const float*)d_in[1];
    const float* bqkv  = (const float*)d_in[2];
    const float* Wproj = (const float*)d_in[3];
    const float* bproj = (const float*)d_in[4];
    float* out = (float*)d_out;

    cudaFuncSetAttribute(attn_mma, cudaFuncAttributeMaxDynamicSharedMemorySize, ATT_SMEM);
    cudaFuncSetAttribute(qkv_mma,  cudaFuncAttributeMaxDynamicSharedMemorySize, SMEM_SZ);
    cudaFuncSetAttribute(proj_mma, cudaFuncAttributeMaxDynamicSharedMemorySize, SMEM_SZ);

    conv_A <<<(MROWS * 96 + 255) / 256, 256>>>(x);
    conv_Wq<<<(C3 * 96 + 255) / 256, 256>>>(Wqkv);
    conv_Wp<<<CC, CC>>>(Wproj);
    qkv_mma<<<dim3(C3 / 128, MROWS / 128), 256, SMEM_SZ>>>(bqkv);
    attn_mma<<<NBH, 416, ATT_SMEM>>>();
    proj_mma<<<dim3(CC / 128, MROWS / 128), 256, SMEM_SZ>>>(bproj, out);
}

// round 11
// speedup vs baseline: 5.9409x; 1.4004x over previous
#include <cuda_runtime.h>
#include <cuda_fp16.h>
#include <math_constants.h>
#include <cstdint>

#define BB 8
#define TT 64
#define NP 196
#define HH 6
#define HD 64
#define CC 384
#define C3 1152
#define BT (BB*TT)           /* 512 */
#define MROWS (BT*NP)        /* 100352 */
#define NBH (BT*HH)          /* 3072 */
#define QK_SCALE 0.125f

#define BK 64
#define NKT 6                /* K = 384, single fp16 pass */
#define STRB 144             /* smem row stride: 64 fp16 + 8 pad */
#define STAGE_BYTES (128*STRB)          /* 18432 */
#define B_REGION (3*STAGE_BYTES)
#define SMEM_SZ (6*STAGE_BYTES)         /* 110592; epilogue (67584) reuses */

/* attention smem: K hi + V hi, 208-row regions (pad rows masked/zeroed) */
#define KSTRB 144
#define SM_KH 0
#define SM_VH 29952          /* 208*144 */
#define ATT_SMEM 59904

/* ---------------- scratch ------------------------------------------------- */
__device__ __half g_Qh[(size_t)NBH*NP*HD];     /* [bh][n][d], pre-scaled */
__device__ __half g_Kh[(size_t)NBH*NP*HD];
__device__ __half g_Vh[(size_t)NBH*NP*HD];
__device__ __half g_Xh[(size_t)MROWS*CC];      /* X fp16 */
__device__ __half g_Ah[(size_t)MROWS*CC];      /* attn out fp16 */
__device__ __half g_Wqc[(size_t)C3*CC];        /* Wqkv fp16 */
__device__ __half g_Wpc[(size_t)CC*CC];        /* Wproj permuted fp16 */

/* ---------------- PTX helpers --------------------------------------------- */
__device__ __forceinline__ uint32_t smem_u32(const void* p) {
    uint32_t a;
    asm("{ .reg .u64 t; cvta.to.shared.u64 t, %1; cvt.u32.u64 %0, t; }" : "=r"(a) : "l"(p));
    return a;
}
__device__ __forceinline__ void cpasync16(uint32_t s, const void* g) {
    asm volatile("cp.async.cg.shared.global [%0], [%1], 16;" :: "r"(s), "l"(g));
}
#define CP_COMMIT() asm volatile("cp.async.commit_group;" ::: "memory")
#define CP_WAIT1()  asm volatile("cp.async.wait_group 1;" ::: "memory")
#define CP_WAIT0()  asm volatile("cp.async.wait_group 0;" ::: "memory")

__device__ __forceinline__ void ldsm_x4(uint32_t* r, uint32_t addr) {
    asm volatile("ldmatrix.sync.aligned.m8n8.x4.shared.b16 {%0,%1,%2,%3}, [%4];"
                 : "=r"(r[0]), "=r"(r[1]), "=r"(r[2]), "=r"(r[3]) : "r"(addr));
}
__device__ __forceinline__ void ldsm_x2(uint32_t* r, uint32_t addr) {
    asm volatile("ldmatrix.sync.aligned.m8n8.x2.shared.b16 {%0,%1}, [%2];"
                 : "=r"(r[0]), "=r"(r[1]) : "r"(addr));
}
__device__ __forceinline__ void ldsm_x2_t(uint32_t* r, uint32_t addr) {
    asm volatile("ldmatrix.sync.aligned.m8n8.x2.trans.shared.b16 {%0,%1}, [%2];"
                 : "=r"(r[0]), "=r"(r[1]) : "r"(addr));
}
__device__ __forceinline__ void mma16816(float* c, const uint32_t* a, const uint32_t* b) {
    asm volatile("mma.sync.aligned.m16n8k16.row.col.f32.f16.f16.f32 "
                 "{%0,%1,%2,%3}, {%4,%5,%6,%7}, {%8,%9}, {%0,%1,%2,%3};"
                 : "+f"(c[0]), "+f"(c[1]), "+f"(c[2]), "+f"(c[3])
                 : "r"(a[0]), "r"(a[1]), "r"(a[2]), "r"(a[3]), "r"(b[0]), "r"(b[1]));
}
__device__ __forceinline__ uint32_t pk2h(__half a, __half b) {
    __half2 t; t.x = a; t.y = b;
    return *(uint32_t*)&t;
}

/* ---------------- conversions (fp16, single) ------------------------------- */
__global__ __launch_bounds__(256) void conv_A(const float* __restrict__ src) {
    int t = blockIdx.x * 256 + threadIdx.x;
    if (t >= MROWS * 96) return;
    float4 v = *(const float4*)(src + (size_t)t * 4);
    uint2 uh;
    uh.x = pk2h(__float2half_rn(v.x), __float2half_rn(v.y));
    uh.y = pk2h(__float2half_rn(v.z), __float2half_rn(v.w));
    *(uint2*)(g_Xh + (size_t)t * 4) = uh;
}
__global__ __launch_bounds__(256) void conv_Wq(const float* __restrict__ src) {
    int t = blockIdx.x * 256 + threadIdx.x;
    if (t >= C3 * 96) return;
    float4 v = *(const float4*)(src + (size_t)t * 4);
    uint2 uh;
    uh.x = pk2h(__float2half_rn(v.x), __float2half_rn(v.y));
    uh.y = pk2h(__float2half_rn(v.z), __float2half_rn(v.w));
    *(uint2*)(g_Wqc + (size_t)t * 4) = uh;
}
__global__ void conv_Wp(const float* __restrict__ src) {
    int o = blockIdx.x, c = threadIdx.x;
    int h = c >> 6, d = c & 63;
    g_Wpc[(size_t)o * CC + c] = __float2half_rn(src[(size_t)o * CC + d * HH + h]);
}

/* ---------------- mma.sync GEMM mainloop (fp16, BK=64, 3-stage, K=384) ----- */
__device__ __forceinline__ void prefetch_kt(const __half* Ab, const __half* Bb,
                                            uint32_t sm, int kt, int tid) {
    const int st = kt % 3;
    const int k0 = kt * 64;
    const uint32_t sa = sm + st * STAGE_BYTES;
    const uint32_t sb = sm + B_REGION + st * STAGE_BYTES;
    #pragma unroll
    for (int it = 0; it < 4; it++) {
        int idx = it * 256 + tid;
        int r = idx >> 3, jj = idx & 7;
        cpasync16(sa + r * STRB + jj * 16, Ab + (size_t)r * CC + k0 + jj * 8);
        cpasync16(sb + r * STRB + jj * 16, Bb + (size_t)r * CC + k0 + jj * 8);
    }
}
__device__ __forceinline__ void gemm_mainloop(const __half* __restrict__ A,
                                              const __half* __restrict__ Bm,
                                              int rowBase, int colBase,
                                              uint32_t sm, float acc[4][4][4]) {
    const int tid  = threadIdx.x;
    const int wid  = tid >> 5, lane = tid & 31;
    const int wr   = wid >> 2, wc = wid & 3;

    #pragma unroll
    for (int i = 0; i < 4; i++)
        #pragma unroll
        for (int j = 0; j < 4; j++)
            #pragma unroll
            for (int k = 0; k < 4; k++) acc[i][j][k] = 0.f;

    const __half* Ab = A + (size_t)rowBase * CC;
    const __half* Bb = Bm + (size_t)colBase * CC;

    prefetch_kt(Ab, Bb, sm, 0, tid); CP_COMMIT();
    prefetch_kt(Ab, Bb, sm, 1, tid); CP_COMMIT();

    const uint32_t aoff = (uint32_t)((wr * 64 + (lane & 15)) * STRB + ((lane >> 4) & 1) * 16);
    const uint32_t boff = (uint32_t)((wc * 32 + (lane & 7) + ((lane >> 4) & 1) * 8) * STRB
                                     + ((lane >> 3) & 1) * 16);

    #pragma unroll 1
    for (int kt = 0; kt < NKT; kt++) {
        CP_WAIT1();
        __syncthreads();
        if (kt + 2 < NKT) prefetch_kt(Ab, Bb, sm, kt + 2, tid);
        CP_COMMIT();

        const int st = kt % 3;
        const uint32_t aBase = sm + st * STAGE_BYTES + aoff;
        const uint32_t bBase = sm + B_REGION + st * STAGE_BYTES + boff;
        #pragma unroll
        for (int ks = 0; ks < 4; ks++) {
            uint32_t af[4][4], bf[2][4];
            #pragma unroll
            for (int i = 0; i < 4; i++)
                ldsm_x4(af[i], aBase + (uint32_t)(i * 16 * STRB + ks * 32));
            #pragma unroll
            for (int jj = 0; jj < 2; jj++)
                ldsm_x4(bf[jj], bBase + (uint32_t)(jj * 16 * STRB + ks * 32));
            #pragma unroll
            for (int i = 0; i < 4; i++) {
                mma16816(acc[i][0], af[i], bf[0]);
                mma16816(acc[i][1], af[i], bf[0] + 2);
                mma16816(acc[i][2], af[i], bf[1]);
                mma16816(acc[i][3], af[i], bf[1] + 2);
            }
        }
    }
    CP_WAIT0();
    __syncthreads();
}

__device__ __forceinline__ void acc_to_smem(float* eps, float acc[4][4][4]) {
    const int tid = threadIdx.x, wid = tid >> 5, lane = tid & 31;
    const int wr = wid >> 2, wc = wid & 3;
    const int rl = lane >> 2, cl = 2 * (lane & 3);
    #pragma unroll
    for (int i = 0; i < 4; i++) {
        #pragma unroll
        for (int j = 0; j < 4; j++) {
            int r = wr * 64 + i * 16 + rl;
            int c = wc * 32 + j * 8 + cl;
            eps[r * 132 + c]       = acc[i][j][0];
            eps[r * 132 + c + 1]   = acc[i][j][1];
            eps[(r + 8) * 132 + c] = acc[i][j][2];
            eps[(r + 8) * 132 + c + 1] = acc[i][j][3];
        }
    }
    __syncthreads();
}

/* ---------------- QKV GEMM kernel ------------------------------------------ */
__global__ __launch_bounds__(256) void qkv_mma(const float* __restrict__ bias) {
    extern __shared__ char dynsm[];
    uint32_t sm = smem_u32(dynsm);
    const int colBase = blockIdx.x * 128;
    const int rowBase = blockIdx.y * 128;
    const int s = colBase / CC;

    float acc[4][4][4];
    gemm_mainloop(g_Xh, g_Wqc, rowBase, colBase, sm, acc);
    float* eps = (float*)dynsm;
    acc_to_smem(eps, acc);

    const int tid = threadIdx.x, w = tid >> 5, lane = tid & 31;
    const int hb = (colBase - s * CC) >> 6;
    const float mul = (s == 0) ? QK_SCALE : 1.0f;
    __half* dst = (s == 0) ? g_Qh : (s == 1) ? g_Kh : g_Vh;
    #pragma unroll
    for (int it = 0; it < 16; it++) {
        int run = (it * 8 + w) * 2 + (lane >> 4);
        int row = run >> 1, hh = run & 1, j = lane & 15;
        int m = rowBase + row;
        int bt = m / NP, n = m - bt * NP;
        float4 v = *(float4*)(eps + row * 132 + hh * 64 + j * 4);
        float4 bv = *(const float4*)(bias + colBase + hh * 64 + j * 4);
        v.x = (v.x + bv.x) * mul; v.y = (v.y + bv.y) * mul;
        v.z = (v.z + bv.z) * mul; v.w = (v.w + bv.w) * mul;
        uint2 uh;
        uh.x = pk2h(__float2half_rn(v.x), __float2half_rn(v.y));
        uh.y = pk2h(__float2half_rn(v.z), __float2half_rn(v.w));
        size_t off = ((size_t)(bt * HH + hb + hh) * NP + n) * HD + j * 4;
        *(uint2*)(dst + off) = uh;
    }
}

/* ---------------- proj GEMM kernel ----------------------------------------- */
__global__ __launch_bounds__(256) void proj_mma(const float* __restrict__ bias,
                                                float* __restrict__ out) {
    extern __shared__ char dynsm[];
    uint32_t sm = smem_u32(dynsm);
    const int colBase = blockIdx.x * 128;
    const int rowBase = blockIdx.y * 128;

    float acc[4][4][4];
    gemm_mainloop(g_Ah, g_Wpc, rowBase, colBase, sm, acc);
    float* eps = (float*)dynsm;
    acc_to_smem(eps, acc);

    const int tid = threadIdx.x, w = tid >> 5, lane = tid & 31;
    float4 bv = *(const float4*)(bias + colBase + lane * 4);
    #pragma unroll
    for (int it = 0; it < 16; it++) {
        int row = it * 8 + w;
        int m = rowBase + row;
        float4 v = *(float4*)(eps + row * 132 + lane * 4);
        v.x += bv.x; v.y += bv.y; v.z += bv.z; v.w += bv.w;
        *(float4*)(out + (size_t)m * CC + colBase + lane * 4) = v;
    }
}

/* ---------------- attention via mma.sync (pure fp16) ----------------------- */
template<int NT>
__device__ __forceinline__ void attn_chunk(uint32_t sb, int lane, int cbase,
                                           const uint32_t qh[4][4],
                                           float o[8][4], float& lp0, float& lp1) {
    float s[NT][4];
    #pragma unroll
    for (int t = 0; t < NT; t++)
        #pragma unroll
        for (int e = 0; e < 4; e++) s[t][e] = 0.f;

    /* --- QK --- */
    #pragma unroll
    for (int t = 0; t < NT; t++) {
        #pragma unroll
        for (int ks = 0; ks < 4; ks++) {
            uint32_t bh[2];
            uint32_t off = (uint32_t)((cbase + t * 8 + (lane & 7)) * KSTRB
                                      + ks * 32 + ((lane >> 3) & 1) * 16);
            ldsm_x2(bh, sb + SM_KH + off);
            mma16816(s[t], qh[ks], bh);
        }
    }

    /* --- exp + mask + pack P (fp16 hi only; l accumulated in fp32) --- */
    uint32_t phi[NT/2][4];
    #pragma unroll
    for (int t = 0; t < NT; t++) {
        int c0 = cbase + t * 8 + 2 * (lane & 3);
        float p0 = (c0     < NP) ? __expf(s[t][0]) : 0.f;
        float p1 = (c0 + 1 < NP) ? __expf(s[t][1]) : 0.f;
        float p2 = (c0     < NP) ? __expf(s[t][2]) : 0.f;
        float p3 = (c0 + 1 < NP) ? __expf(s[t][3]) : 0.f;
        lp0 += p0 + p1;
        lp1 += p2 + p3;
        int j = t >> 1, oreg = (t & 1) * 2;
        phi[j][oreg]     = pk2h(__float2half_rn(p0), __float2half_rn(p1));
        phi[j][oreg + 1] = pk2h(__float2half_rn(p2), __float2half_rn(p3));
    }

    /* --- PV: b-frags via ldmatrix.trans on V rows [n][d] --- */
    #pragma unroll
    for (int j = 0; j < NT / 2; j++) {
        #pragma unroll
        for (int nd = 0; nd < 8; nd++) {
            uint32_t bh[2];
            uint32_t off = (uint32_t)((cbase + j * 16 + (lane & 15)) * KSTRB + nd * 16);
            ldsm_x2_t(bh, sb + SM_VH + off);
            mma16816(o[nd], phi[j], bh);
        }
    }
}

__global__ __launch_bounds__(416, 1) void attn_mma() {
    extern __shared__ char smc[];
    uint32_t sb = smem_u32(smc);
    const int bx = blockIdx.x;                 /* bt*6 + h */
    const int tid = threadIdx.x, wid = tid >> 5, lane = tid & 31;

    const size_t base = (size_t)bx * NP * HD;
    for (int i = tid; i < NP * 8; i += 416) {
        int r = i >> 3, j = i & 7;
        uint32_t doff = (uint32_t)(r * KSTRB + j * 16);
        *(uint4*)(smc + SM_KH + doff) = ((const uint4*)(g_Kh + base))[i];
        *(uint4*)(smc + SM_VH + doff) = ((const uint4*)(g_Vh + base))[i];
    }
    /* zero V pad rows 196-207 (NaN x 0 guard in PV) */
    if (tid < 108)
        *(uint4*)(smc + SM_VH + 196 * KSTRB + tid * 16) = make_uint4(0, 0, 0, 0);

    /* Q fragments straight from gmem (row-clamped) */
    uint32_t qh[4][4];
    {
        const uint32_t* qhp = (const uint32_t*)(g_Qh + base);
        int r  = wid * 16 + (lane >> 2);
        int r2 = r + 8;
        int ra  = (r  < NP) ? r  : NP - 1;
        int r2a = (r2 < NP) ? r2 : NP - 1;
        int c = lane & 3;
        #pragma unroll
        for (int ks = 0; ks < 4; ks++) {
            qh[ks][0] = qhp[ra  * 32 + ks * 8 + c];
            qh[ks][1] = qhp[r2a * 32 + ks * 8 + c];
            qh[ks][2] = qhp[ra  * 32 + ks * 8 + 4 + c];
            qh[ks][3] = qhp[r2a * 32 + ks * 8 + 4 + c];
        }
    }
    __syncthreads();

    float o[8][4];
    #pragma unroll
    for (int nd = 0; nd < 8; nd++)
        #pragma unroll
        for (int e = 0; e < 4; e++) o[nd][e] = 0.f;
    float lp0 = 0.f, lp1 = 0.f;

    attn_chunk<14>(sb, lane, 0,   qh, o, lp0, lp1);
    attn_chunk<12>(sb, lane, 112, qh, o, lp0, lp1);

    lp0 += __shfl_xor_sync(0xFFFFFFFFu, lp0, 1);
    lp0 += __shfl_xor_sync(0xFFFFFFFFu, lp0, 2);
    lp1 += __shfl_xor_sync(0xFFFFFFFFu, lp1, 1);
    lp1 += __shfl_xor_sync(0xFFFFFFFFu, lp1, 2);
    const float inv0 = 1.0f / lp0, inv1 = 1.0f / lp1;

    const int bt = bx / HH, h = bx - bt * HH;
    const int r0 = wid * 16 + (lane >> 2);
    const int cl = 2 * (lane & 3);
    #pragma unroll
    for (int nd = 0; nd < 8; nd++) {
        int col = h * HD + nd * 8 + cl;
        if (r0 < NP) {
            size_t ro = ((size_t)bt * NP + r0) * CC + col;
            *(uint32_t*)(g_Ah + ro) = pk2h(__float2half_rn(o[nd][0] * inv0),
                                           __float2half_rn(o[nd][1] * inv0));
        }
        if (r0 + 8 < NP) {
            size_t ro = ((size_t)bt * NP + r0 + 8) * CC + col;
            *(uint32_t*)(g_Ah + ro) = pk2h(__float2half_rn(o[nd][2] * inv1),
                                           __float2half_rn(o[nd][3] * inv1));
        }
    }
}

/* ---------------- launch --------------------------------------------------- */
extern "C" void kernel_launch(void* const* d_in, const int* in_sizes, int n_in,
                              void* d_out, int out_size) {
    const float* x     = (const float*)d_in[0];
    const float* Wqkv  = (const float*)d_in[1];
    const float* bqkv  = (const float*)d_in[2];
    const float* Wproj = (const float*)d_in[3];
    const float* bproj = (const float*)d_in[4];
    float* out = (float*)d_out;

    cudaFuncSetAttribute(attn_mma, cudaFuncAttributeMaxDynamicSharedMemorySize, ATT_SMEM);
    cudaFuncSetAttribute(qkv_mma,  cudaFuncAttributeMaxDynamicSharedMemorySize, SMEM_SZ);
    cudaFuncSetAttribute(proj_mma, cudaFuncAttributeMaxDynamicSharedMemorySize, SMEM_SZ);

    conv_A <<<(MROWS * 96 + 255) / 256, 256>>>(x);
    conv_Wq<<<(C3 * 96 + 255) / 256, 256>>>(Wqkv);
    conv_Wp<<<CC, CC>>>(Wproj);
    qkv_mma<<<dim3(C3 / 128, MROWS / 128), 256, SMEM_SZ>>>(bqkv);
    attn_mma<<<NBH, 416, ATT_SMEM>>>();
    proj_mma<<<dim3(CC / 128, MROWS / 128), 256, SMEM_SZ>>>(bproj, out);
}

// round 12
// speedup vs baseline: 6.2527x; 1.0525x over previous
#include <cuda_runtime.h>
#include <cuda_fp16.h>
#include <math_constants.h>
#include <cstdint>

#define BB 8
#define TT 64
#define NP 196
#define HH 6
#define HD 64
#define CC 384
#define C3 1152
#define BT (BB*TT)           /* 512 */
#define MROWS (BT*NP)        /* 100352 */
#define NBH (BT*HH)          /* 3072 */
#define QK_SCALE 0.125f

#define BK 64
#define NKT 6                /* K = 384, single fp16 pass */
#define STRB 144             /* smem row stride: 64 fp16 + 8 pad */
#define STAGE_BYTES (128*STRB)          /* 18432 */
#define B_REGION (3*STAGE_BYTES)
#define SMEM_SZ (6*STAGE_BYTES)         /* 110592 */

/* attention smem: K + V, 208-row regions */
#define KSTRB 144
#define SM_KH 0
#define SM_VH 29952          /* 208*144 */
#define ATT_SMEM 59904

/* merged conv grid split */
#define NBLK_A  (MROWS*96/256)   /* 37632 */
#define NBLK_WQ (C3*96/256)      /* 432 */
#define NBLK_WP (CC*CC/256)      /* 576 */

/* ---------------- scratch ------------------------------------------------- */
__device__ __half g_Qh[(size_t)NBH*NP*HD];     /* [bh][n][d], pre-scaled */
__device__ __half g_Kh[(size_t)NBH*NP*HD];
__device__ __half g_Vh[(size_t)NBH*NP*HD];
__device__ __half g_Xh[(size_t)MROWS*CC];      /* X fp16 */
__device__ __half g_Ah[(size_t)MROWS*CC];      /* attn out fp16 */
__device__ __half g_Wqc[(size_t)C3*CC];        /* Wqkv fp16 */
__device__ __half g_Wpc[(size_t)CC*CC];        /* Wproj permuted fp16 */

/* ---------------- PTX helpers --------------------------------------------- */
__device__ __forceinline__ uint32_t smem_u32(const void* p) {
    uint32_t a;
    asm("{ .reg .u64 t; cvta.to.shared.u64 t, %1; cvt.u32.u64 %0, t; }" : "=r"(a) : "l"(p));
    return a;
}
__device__ __forceinline__ void cpasync16(uint32_t s, const void* g) {
    asm volatile("cp.async.cg.shared.global [%0], [%1], 16;" :: "r"(s), "l"(g));
}
#define CP_COMMIT() asm volatile("cp.async.commit_group;" ::: "memory")
#define CP_WAIT1()  asm volatile("cp.async.wait_group 1;" ::: "memory")
#define CP_WAIT0()  asm volatile("cp.async.wait_group 0;" ::: "memory")

__device__ __forceinline__ void ldsm_x4(uint32_t* r, uint32_t addr) {
    asm volatile("ldmatrix.sync.aligned.m8n8.x4.shared.b16 {%0,%1,%2,%3}, [%4];"
                 : "=r"(r[0]), "=r"(r[1]), "=r"(r[2]), "=r"(r[3]) : "r"(addr));
}
__device__ __forceinline__ void ldsm_x2(uint32_t* r, uint32_t addr) {
    asm volatile("ldmatrix.sync.aligned.m8n8.x2.shared.b16 {%0,%1}, [%2];"
                 : "=r"(r[0]), "=r"(r[1]) : "r"(addr));
}
__device__ __forceinline__ void ldsm_x2_t(uint32_t* r, uint32_t addr) {
    asm volatile("ldmatrix.sync.aligned.m8n8.x2.trans.shared.b16 {%0,%1}, [%2];"
                 : "=r"(r[0]), "=r"(r[1]) : "r"(addr));
}
__device__ __forceinline__ void mma16816(float* c, const uint32_t* a, const uint32_t* b) {
    asm volatile("mma.sync.aligned.m16n8k16.row.col.f32.f16.f16.f32 "
                 "{%0,%1,%2,%3}, {%4,%5,%6,%7}, {%8,%9}, {%0,%1,%2,%3};"
                 : "+f"(c[0]), "+f"(c[1]), "+f"(c[2]), "+f"(c[3])
                 : "r"(a[0]), "r"(a[1]), "r"(a[2]), "r"(a[3]), "r"(b[0]), "r"(b[1]));
}
__device__ __forceinline__ uint32_t pk2h(__half a, __half b) {
    __half2 t; t.x = a; t.y = b;
    return *(uint32_t*)&t;
}

/* ---------------- merged conversions --------------------------------------- */
__global__ __launch_bounds__(256) void conv_all(const float* __restrict__ x,
                                                const float* __restrict__ Wq,
                                                const float* __restrict__ Wp) {
    int b = blockIdx.x;
    if (b < NBLK_A) {
        int t = b * 256 + threadIdx.x;
        float4 v = *(const float4*)(x + (size_t)t * 4);
        uint2 uh;
        uh.x = pk2h(__float2half_rn(v.x), __float2half_rn(v.y));
        uh.y = pk2h(__float2half_rn(v.z), __float2half_rn(v.w));
        *(uint2*)(g_Xh + (size_t)t * 4) = uh;
    } else if (b < NBLK_A + NBLK_WQ) {
        int t = (b - NBLK_A) * 256 + threadIdx.x;
        float4 v = *(const float4*)(Wq + (size_t)t * 4);
        uint2 uh;
        uh.x = pk2h(__float2half_rn(v.x), __float2half_rn(v.y));
        uh.y = pk2h(__float2half_rn(v.z), __float2half_rn(v.w));
        *(uint2*)(g_Wqc + (size_t)t * 4) = uh;
    } else {
        int t = (b - NBLK_A - NBLK_WQ) * 256 + threadIdx.x;
        int o = t / CC, c = t - o * CC;
        int h = c >> 6, d = c & 63;
        g_Wpc[(size_t)o * CC + c] = __float2half_rn(Wp[(size_t)o * CC + d * HH + h]);
    }
}

/* ---------------- mma.sync GEMM mainloop (fp16, BK=64, 3-stage, K=384) ----- */
__device__ __forceinline__ void prefetch_kt(const __half* Ab, const __half* Bb,
                                            uint32_t sm, int kt, int tid) {
    const int st = kt % 3;
    const int k0 = kt * 64;
    const uint32_t sa = sm + st * STAGE_BYTES;
    const uint32_t sb = sm + B_REGION + st * STAGE_BYTES;
    #pragma unroll
    for (int it = 0; it < 4; it++) {
        int idx = it * 256 + tid;
        int r = idx >> 3, jj = idx & 7;
        cpasync16(sa + r * STRB + jj * 16, Ab + (size_t)r * CC + k0 + jj * 8);
        cpasync16(sb + r * STRB + jj * 16, Bb + (size_t)r * CC + k0 + jj * 8);
    }
}
__device__ __forceinline__ void gemm_mainloop(const __half* __restrict__ A,
                                              const __half* __restrict__ Bm,
                                              int rowBase, int colBase,
                                              uint32_t sm, float acc[4][4][4]) {
    const int tid  = threadIdx.x;
    const int wid  = tid >> 5, lane = tid & 31;
    const int wr   = wid >> 2, wc = wid & 3;

    #pragma unroll
    for (int i = 0; i < 4; i++)
        #pragma unroll
        for (int j = 0; j < 4; j++)
            #pragma unroll
            for (int k = 0; k < 4; k++) acc[i][j][k] = 0.f;

    const __half* Ab = A + (size_t)rowBase * CC;
    const __half* Bb = Bm + (size_t)colBase * CC;

    prefetch_kt(Ab, Bb, sm, 0, tid); CP_COMMIT();
    prefetch_kt(Ab, Bb, sm, 1, tid); CP_COMMIT();

    const uint32_t aoff = (uint32_t)((wr * 64 + (lane & 15)) * STRB + ((lane >> 4) & 1) * 16);
    const uint32_t boff = (uint32_t)((wc * 32 + (lane & 7) + ((lane >> 4) & 1) * 8) * STRB
                                     + ((lane >> 3) & 1) * 16);

    #pragma unroll 1
    for (int kt = 0; kt < NKT; kt++) {
        CP_WAIT1();
        __syncthreads();
        if (kt + 2 < NKT) prefetch_kt(Ab, Bb, sm, kt + 2, tid);
        CP_COMMIT();

        const int st = kt % 3;
        const uint32_t aBase = sm + st * STAGE_BYTES + aoff;
        const uint32_t bBase = sm + B_REGION + st * STAGE_BYTES + boff;
        #pragma unroll
        for (int ks = 0; ks < 4; ks++) {
            uint32_t af[4][4], bf[2][4];
            #pragma unroll
            for (int jj = 0; jj < 2; jj++)
                ldsm_x4(bf[jj], bBase + (uint32_t)(jj * 16 * STRB + ks * 32));
            #pragma unroll
            for (int i = 0; i < 4; i++)
                ldsm_x4(af[i], aBase + (uint32_t)(i * 16 * STRB + ks * 32));
            #pragma unroll
            for (int i = 0; i < 4; i++) {
                mma16816(acc[i][0], af[i], bf[0]);
                mma16816(acc[i][1], af[i], bf[0] + 2);
                mma16816(acc[i][2], af[i], bf[1]);
                mma16816(acc[i][3], af[i], bf[1] + 2);
            }
        }
    }
    CP_WAIT0();
    __syncthreads();
}

/* ---------------- QKV GEMM kernel (direct-STG epilogue) -------------------- */
__global__ __launch_bounds__(256) void qkv_mma(const float* __restrict__ bias) {
    extern __shared__ char dynsm[];
    uint32_t sm = smem_u32(dynsm);
    const int colBase = blockIdx.x * 128;
    const int rowBase = blockIdx.y * 128;
    const int s = colBase / CC;

    float acc[4][4][4];
    gemm_mainloop(g_Xh, g_Wqc, rowBase, colBase, sm, acc);

    const int tid = threadIdx.x, wid = tid >> 5, lane = tid & 31;
    const int wr = wid >> 2, wc = wid & 3;
    const int rl = lane >> 2, cl = 2 * (lane & 3);
    const int hb = (colBase - s * CC) >> 6;
    const float mul = (s == 0) ? QK_SCALE : 1.0f;
    __half* dst = (s == 0) ? g_Qh : (s == 1) ? g_Kh : g_Vh;

    float2 bj[4];
    #pragma unroll
    for (int j = 0; j < 4; j++)
        bj[j] = *(const float2*)(bias + colBase + wc * 32 + j * 8 + cl);

    #pragma unroll
    for (int i = 0; i < 4; i++) {
        int m0 = rowBase + wr * 64 + i * 16 + rl;
        int m1 = m0 + 8;
        int bt0 = m0 / NP, n0 = m0 - bt0 * NP;
        int bt1 = m1 / NP, n1 = m1 - bt1 * NP;
        #pragma unroll
        for (int j = 0; j < 4; j++) {
            int c = wc * 32 + j * 8 + cl;
            int hh = c >> 6, d = c & 63;
            float v0 = (acc[i][j][0] + bj[j].x) * mul;
            float v1 = (acc[i][j][1] + bj[j].y) * mul;
            float v2 = (acc[i][j][2] + bj[j].x) * mul;
            float v3 = (acc[i][j][3] + bj[j].y) * mul;
            size_t o0 = ((size_t)(bt0 * HH + hb + hh) * NP + n0) * HD + d;
            size_t o1 = ((size_t)(bt1 * HH + hb + hh) * NP + n1) * HD + d;
            *(uint32_t*)(dst + o0) = pk2h(__float2half_rn(v0), __float2half_rn(v1));
            *(uint32_t*)(dst + o1) = pk2h(__float2half_rn(v2), __float2half_rn(v3));
        }
    }
}

/* ---------------- proj GEMM kernel (direct-STG epilogue) ------------------- */
__global__ __launch_bounds__(256) void proj_mma(const float* __restrict__ bias,
                                                float* __restrict__ out) {
    extern __shared__ char dynsm[];
    uint32_t sm = smem_u32(dynsm);
    const int colBase = blockIdx.x * 128;
    const int rowBase = blockIdx.y * 128;

    float acc[4][4][4];
    gemm_mainloop(g_Ah, g_Wpc, rowBase, colBase, sm, acc);

    const int tid = threadIdx.x, wid = tid >> 5, lane = tid & 31;
    const int wr = wid >> 2, wc = wid & 3;
    const int rl = lane >> 2, cl = 2 * (lane & 3);

    float2 bj[4];
    #pragma unroll
    for (int j = 0; j < 4; j++)
        bj[j] = *(const float2*)(bias + colBase + wc * 32 + j * 8 + cl);

    #pragma unroll
    for (int i = 0; i < 4; i++) {
        int m0 = rowBase + wr * 64 + i * 16 + rl;
        int m1 = m0 + 8;
        #pragma unroll
        for (int j = 0; j < 4; j++) {
            int col = colBase + wc * 32 + j * 8 + cl;
            float2 v0; v0.x = acc[i][j][0] + bj[j].x; v0.y = acc[i][j][1] + bj[j].y;
            float2 v1; v1.x = acc[i][j][2] + bj[j].x; v1.y = acc[i][j][3] + bj[j].y;
            *(float2*)(out + (size_t)m0 * CC + col) = v0;
            *(float2*)(out + (size_t)m1 * CC + col) = v1;
        }
    }
}

/* ---------------- attention via mma.sync (pure fp16) ----------------------- */
template<int NT>
__device__ __forceinline__ void attn_chunk(uint32_t sb, int lane, int cbase,
                                           const uint32_t qh[4][4],
                                           float o[8][4], float& lp0, float& lp1) {
    float s[NT][4];
    #pragma unroll
    for (int t = 0; t < NT; t++)
        #pragma unroll
        for (int e = 0; e < 4; e++) s[t][e] = 0.f;

    /* --- QK --- */
    #pragma unroll
    for (int t = 0; t < NT; t++) {
        #pragma unroll
        for (int ks = 0; ks < 4; ks++) {
            uint32_t bh[2];
            uint32_t off = (uint32_t)((cbase + t * 8 + (lane & 7)) * KSTRB
                                      + ks * 32 + ((lane >> 3) & 1) * 16);
            ldsm_x2(bh, sb + SM_KH + off);
            mma16816(s[t], qh[ks], bh);
        }
    }

    /* --- exp + mask + pack P --- */
    uint32_t phi[NT/2][4];
    #pragma unroll
    for (int t = 0; t < NT; t++) {
        int c0 = cbase + t * 8 + 2 * (lane & 3);
        float p0 = (c0     < NP) ? __expf(s[t][0]) : 0.f;
        float p1 = (c0 + 1 < NP) ? __expf(s[t][1]) : 0.f;
        float p2 = (c0     < NP) ? __expf(s[t][2]) : 0.f;
        float p3 = (c0 + 1 < NP) ? __expf(s[t][3]) : 0.f;
        lp0 += p0 + p1;
        lp1 += p2 + p3;
        int j = t >> 1, oreg = (t & 1) * 2;
        phi[j][oreg]     = pk2h(__float2half_rn(p0), __float2half_rn(p1));
        phi[j][oreg + 1] = pk2h(__float2half_rn(p2), __float2half_rn(p3));
    }

    /* --- PV: b-frags via ldmatrix.trans on V rows [n][d] --- */
    #pragma unroll
    for (int j = 0; j < NT / 2; j++) {
        #pragma unroll
        for (int nd = 0; nd < 8; nd++) {
            uint32_t bh[2];
            uint32_t off = (uint32_t)((cbase + j * 16 + (lane & 15)) * KSTRB + nd * 16);
            ldsm_x2_t(bh, sb + SM_VH + off);
            mma16816(o[nd], phi[j], bh);
        }
    }
}

__global__ __launch_bounds__(416, 1) void attn_mma() {
    extern __shared__ char smc[];
    uint32_t sb = smem_u32(smc);
    const int bx = blockIdx.x;                 /* bt*6 + h */
    const int tid = threadIdx.x, wid = tid >> 5, lane = tid & 31;

    const size_t base = (size_t)bx * NP * HD;
    /* K/V copy-in via cp.async (overlaps with Q-frag LDGs below) */
    for (int i = tid; i < NP * 8; i += 416) {
        int r = i >> 3, j = i & 7;
        uint32_t doff = (uint32_t)(r * KSTRB + j * 16);
        cpasync16(sb + SM_KH + doff, (const uint4*)(g_Kh + base) + i);
        cpasync16(sb + SM_VH + doff, (const uint4*)(g_Vh + base) + i);
    }
    CP_COMMIT();
    /* zero V pad rows 196-207 (NaN x 0 guard in PV) */
    if (tid < 108)
        *(uint4*)(smc + SM_VH + 196 * KSTRB + tid * 16) = make_uint4(0, 0, 0, 0);

    /* Q fragments straight from gmem (row-clamped) */
    uint32_t qh[4][4];
    {
        const uint32_t* qhp = (const uint32_t*)(g_Qh + base);
        int r  = wid * 16 + (lane >> 2);
        int r2 = r + 8;
        int ra  = (r  < NP) ? r  : NP - 1;
        int r2a = (r2 < NP) ? r2 : NP - 1;
        int c = lane & 3;
        #pragma unroll
        for (int ks = 0; ks < 4; ks++) {
            qh[ks][0] = qhp[ra  * 32 + ks * 8 + c];
            qh[ks][1] = qhp[r2a * 32 + ks * 8 + c];
            qh[ks][2] = qhp[ra  * 32 + ks * 8 + 4 + c];
            qh[ks][3] = qhp[r2a * 32 + ks * 8 + 4 + c];
        }
    }
    CP_WAIT0();
    __syncthreads();

    float o[8][4];
    #pragma unroll
    for (int nd = 0; nd < 8; nd++)
        #pragma unroll
        for (int e = 0; e < 4; e++) o[nd][e] = 0.f;
    float lp0 = 0.f, lp1 = 0.f;

    attn_chunk<14>(sb, lane, 0,   qh, o, lp0, lp1);
    attn_chunk<12>(sb, lane, 112, qh, o, lp0, lp1);

    lp0 += __shfl_xor_sync(0xFFFFFFFFu, lp0, 1);
    lp0 += __shfl_xor_sync(0xFFFFFFFFu, lp0, 2);
    lp1 += __shfl_xor_sync(0xFFFFFFFFu, lp1, 1);
    lp1 += __shfl_xor_sync(0xFFFFFFFFu, lp1, 2);
    const float inv0 = 1.0f / lp0, inv1 = 1.0f / lp1;

    const int bt = bx / HH, h = bx - bt * HH;
    const int r0 = wid * 16 + (lane >> 2);
    const int cl = 2 * (lane & 3);
    #pragma unroll
    for (int nd = 0; nd < 8; nd++) {
        int col = h * HD + nd * 8 + cl;
        if (r0 < NP) {
            size_t ro = ((size_t)bt * NP + r0) * CC + col;
            *(uint32_t*)(g_Ah + ro) = pk2h(__float2half_rn(o[nd][0] * inv0),
                                           __float2half_rn(o[nd][1] * inv0));
        }
        if (r0 + 8 < NP) {
            size_t ro = ((size_t)bt * NP + r0 + 8) * CC + col;
            *(uint32_t*)(g_Ah + ro) = pk2h(__float2half_rn(o[nd][2] * inv1),
                                           __float2half_rn(o[nd][3] * inv1));
        }
    }
}

/* ---------------- launch --------------------------------------------------- */
extern "C" void kernel_launch(void* const* d_in, const int* in_sizes, int n_in,
                              void* d_out, int out_size) {
    const float* x     = (const float*)d_in[0];
    const float* Wqkv  = (const float*)d_in[1];
    const float* bqkv  = (const float*)d_in[2];
    const float* Wproj = (const float*)d_in[3];
    const float* bproj = (const float*)d_in[4];
    float* out = (float*)d_out;

    cudaFuncSetAttribute(attn_mma, cudaFuncAttributeMaxDynamicSharedMemorySize, ATT_SMEM);
    cudaFuncSetAttribute(qkv_mma,  cudaFuncAttributeMaxDynamicSharedMemorySize, SMEM_SZ);
    cudaFuncSetAttribute(proj_mma, cudaFuncAttributeMaxDynamicSharedMemorySize, SMEM_SZ);

    conv_all<<<NBLK_A + NBLK_WQ + NBLK_WP, 256>>>(x, Wqkv, Wproj);
    qkv_mma<<<dim3(C3 / 128, MROWS / 128), 256, SMEM_SZ>>>(bqkv);
    attn_mma<<<NBH, 416, ATT_SMEM>>>();
    proj_mma<<<dim3(CC / 128, MROWS / 128), 256, SMEM_SZ>>>(bproj, out);
}